// round 1
// baseline (speedup 1.0000x reference)
#include <cuda_runtime.h>
#include <math.h>

// Problem constants (shapes are fixed for this problem instance)
#define BV      4
#define SEQ     4096
#define DIM     1024
#define WIN     512
#define HEADS   16
#define DH      64
#define MROWS   (BV * SEQ)     // 16384
#define N3      (3 * DIM)      // 3072
#define NEG_INF_F (-1e9f)

// Scratch (device globals are the sanctioned workaround for no-alloc rule)
__device__ float g_qkv[(size_t)MROWS * N3];    // 192 MB
__device__ float g_attn[(size_t)MROWS * DIM];  //  64 MB

// ---------------------------------------------------------------------------
// SGEMM + bias: C[M,N] = A[M,K] @ B[K,N] + bias[N]
// 128x128 tile, BK=8, 256 threads, 8x8 per-thread microtile.
// M,N multiples of 128; K multiple of 8 (holds for both GEMMs here).
// ---------------------------------------------------------------------------
__global__ __launch_bounds__(256) void sgemm_bias_kernel(
    const float* __restrict__ A, const float* __restrict__ B,
    const float* __restrict__ bias, float* __restrict__ C,
    int M, int N, int K)
{
    __shared__ float As[8][128];   // transposed A tile: As[k][m]
    __shared__ float Bs[8][128];

    const int tid = threadIdx.x;
    const int tx = tid & 15;       // 0..15 -> N microtiles
    const int ty = tid >> 4;       // 0..15 -> M microtiles
    const int row0 = blockIdx.y * 128;
    const int col0 = blockIdx.x * 128;

    float acc[8][8];
#pragma unroll
    for (int i = 0; i < 8; i++)
#pragma unroll
        for (int j = 0; j < 8; j++) acc[i][j] = 0.f;

    const int arow = tid >> 1;          // 0..127
    const int acol = (tid & 1) * 4;     // 0 or 4
    const int brow = tid >> 5;          // 0..7
    const int bcol = (tid & 31) * 4;    // 0..124

    const float* Aptr = A + (size_t)(row0 + arow) * K + acol;
    const float* Bptr = B + (size_t)brow * N + col0 + bcol;

    for (int k0 = 0; k0 < K; k0 += 8) {
        float4 av = *(const float4*)(Aptr + k0);
        As[acol + 0][arow] = av.x;
        As[acol + 1][arow] = av.y;
        As[acol + 2][arow] = av.z;
        As[acol + 3][arow] = av.w;
        float4 bv = *(const float4*)(Bptr + (size_t)k0 * N);
        *(float4*)&Bs[brow][bcol] = bv;
        __syncthreads();

#pragma unroll
        for (int k = 0; k < 8; k++) {
            float ra[8], rb[8];
            *(float4*)&ra[0] = *(const float4*)&As[k][ty * 8];
            *(float4*)&ra[4] = *(const float4*)&As[k][ty * 8 + 4];
            *(float4*)&rb[0] = *(const float4*)&Bs[k][tx * 8];
            *(float4*)&rb[4] = *(const float4*)&Bs[k][tx * 8 + 4];
#pragma unroll
            for (int i = 0; i < 8; i++)
#pragma unroll
                for (int j = 0; j < 8; j++)
                    acc[i][j] += ra[i] * rb[j];
        }
        __syncthreads();
    }

#pragma unroll
    for (int i = 0; i < 8; i++) {
        size_t r = (size_t)(row0 + ty * 8 + i);
#pragma unroll
        for (int j = 0; j < 8; j += 4) {
            int c = col0 + tx * 8 + j;
            float4 v;
            v.x = acc[i][j + 0] + bias[c + 0];
            v.y = acc[i][j + 1] + bias[c + 1];
            v.z = acc[i][j + 2] + bias[c + 2];
            v.w = acc[i][j + 3] + bias[c + 3];
            *(float4*)&C[r * N + c] = v;
        }
    }
}

// ---------------------------------------------------------------------------
// Windowed causal attention (flash-style, fp32).
// Grid: (16 q-tiles of 32 rows, 512 = 32 windows * 16 heads). Block: 256.
// Per block: Q tile [32 x 64]; loop K/V tiles [64 x 64] with online softmax.
// P (exp scores) aliases the K smem buffer to stay under 48 KB static smem.
// Thread (ty,tx): owns S rows {ty*2, ty*2+1}, S cols tx*4..tx*4+3,
//                 and O rows {ty*2,ty*2+1}, d-cols tx*4..tx*4+3.
// Row reductions: 16-lane shuffle groups (all tx for a given ty share a
// half-warp since tid = ty*16 + tx).
// ---------------------------------------------------------------------------
__global__ __launch_bounds__(256) void attn_kernel(
    const float* __restrict__ qkv, float* __restrict__ outp)
{
    const int qt   = blockIdx.x;       // 0..15
    const int pair = blockIdx.y;       // 0..511
    const int bn   = pair >> 4;        // window index 0..31
    const int h    = pair & 15;        // head
    const int tid  = threadIdx.x;
    const int tx   = tid & 15;
    const int ty   = tid >> 4;
    const int mbase = bn * WIN;
    const int qcol  = h * DH;

    __shared__ float Qs[32 * 65];      // padded: bank-friendly row reads
    __shared__ float KPs[64 * 65];     // K tile, later reused for P (rows 0..31)
    __shared__ float Vs[64 * 64];      // unpadded: float4 row reads

    // Load Q tile (coalesced global reads, scalar smem stores into padded buf)
    for (int idx = tid; idx < 32 * 64; idx += 256) {
        int r = idx >> 6, c = idx & 63;
        Qs[r * 65 + c] = qkv[(size_t)(mbase + qt * 32 + r) * N3 + qcol + c];
    }

    float m_i[2] = { -INFINITY, -INFINITY };
    float l_i[2] = { 0.f, 0.f };
    float o_acc[2][4] = {};

    const int gq0 = qt * 32 + ty * 2;             // window-local q row (i=0)
    const int ktmax = (qt * 32 + 31) >> 6;        // last K tile touching diag
    __syncthreads();

    for (int kt = 0; kt <= ktmax; kt++) {
        // Load K and V tiles [64 x 64]
        for (int idx = tid; idx < 64 * 64; idx += 256) {
            int r = idx >> 6, c = idx & 63;
            size_t g = (size_t)(mbase + kt * 64 + r) * N3 + qcol + c;
            KPs[r * 65 + c] = qkv[g + DIM];       // K
            Vs[idx]         = qkv[g + 2 * DIM];   // V
        }
        __syncthreads();

        // S = Q K^T (per-thread 2x4)
        float s[2][4];
#pragma unroll
        for (int i = 0; i < 2; i++)
#pragma unroll
            for (int j = 0; j < 4; j++) s[i][j] = 0.f;

#pragma unroll 8
        for (int d = 0; d < 64; d++) {
            float ra0 = Qs[(ty * 2 + 0) * 65 + d];
            float ra1 = Qs[(ty * 2 + 1) * 65 + d];
#pragma unroll
            for (int j = 0; j < 4; j++) {
                float rb = KPs[(tx * 4 + j) * 65 + d];
                s[0][j] += ra0 * rb;
                s[1][j] += ra1 * rb;
            }
        }
        __syncthreads();   // all K reads done; KPs can be overwritten with P

        // scale + causal mask + online softmax, write P into KPs rows 0..31
#pragma unroll
        for (int i = 0; i < 2; i++) {
            const int gq = gq0 + i;
#pragma unroll
            for (int j = 0; j < 4; j++) {
                int gk = kt * 64 + tx * 4 + j;
                float v = s[i][j] * 0.125f;       // 1/sqrt(64)
                s[i][j] = (gk > gq) ? NEG_INF_F : v;
            }
            float rm = fmaxf(fmaxf(s[i][0], s[i][1]), fmaxf(s[i][2], s[i][3]));
#pragma unroll
            for (int o = 1; o < 16; o <<= 1)
                rm = fmaxf(rm, __shfl_xor_sync(0xffffffffu, rm, o));
            float mn   = fmaxf(m_i[i], rm);
            float corr = __expf(m_i[i] - mn);     // 0 when m_i = -inf
            float rs = 0.f;
#pragma unroll
            for (int j = 0; j < 4; j++) {
                float p = __expf(s[i][j] - mn);
                s[i][j] = p;
                rs += p;
            }
#pragma unroll
            for (int o = 1; o < 16; o <<= 1)
                rs += __shfl_xor_sync(0xffffffffu, rs, o);
            l_i[i] = l_i[i] * corr + rs;
            m_i[i] = mn;
#pragma unroll
            for (int j = 0; j < 4; j++) o_acc[i][j] *= corr;
#pragma unroll
            for (int j = 0; j < 4; j++)
                KPs[(ty * 2 + i) * 65 + tx * 4 + j] = s[i][j];
        }
        __syncthreads();

        // O += P @ V  (per-thread 2x4 over k=0..63)
#pragma unroll 8
        for (int k = 0; k < 64; k++) {
            float ra0 = KPs[(ty * 2 + 0) * 65 + k];
            float ra1 = KPs[(ty * 2 + 1) * 65 + k];
            float4 rb = *(const float4*)&Vs[k * 64 + tx * 4];
            o_acc[0][0] += ra0 * rb.x; o_acc[0][1] += ra0 * rb.y;
            o_acc[0][2] += ra0 * rb.z; o_acc[0][3] += ra0 * rb.w;
            o_acc[1][0] += ra1 * rb.x; o_acc[1][1] += ra1 * rb.y;
            o_acc[1][2] += ra1 * rb.z; o_acc[1][3] += ra1 * rb.w;
        }
        __syncthreads();   // before next tile overwrites KPs/Vs
    }

    // Normalize + write (head-major columns: matches transpose+reshape)
#pragma unroll
    for (int i = 0; i < 2; i++) {
        float inv = 1.f / l_i[i];
        size_t r = (size_t)(mbase + qt * 32 + ty * 2 + i);
#pragma unroll
        for (int j = 0; j < 4; j++)
            outp[r * DIM + qcol + tx * 4 + j] = o_acc[i][j] * inv;
    }
}

// ---------------------------------------------------------------------------
extern "C" void kernel_launch(void* const* d_in, const int* in_sizes, int n_in,
                              void* d_out, int out_size)
{
    (void)in_sizes; (void)n_in; (void)out_size;
    const float* x     = (const float*)d_in[0];
    const float* w_qkv = (const float*)d_in[1];
    const float* b_qkv = (const float*)d_in[2];
    const float* w_o   = (const float*)d_in[3];
    const float* b_o   = (const float*)d_in[4];
    float* out = (float*)d_out;

    float *qkv_p, *attn_p;
    cudaGetSymbolAddress((void**)&qkv_p,  g_qkv);
    cudaGetSymbolAddress((void**)&attn_p, g_attn);

    // 1) QKV projection: [16384,1024] @ [1024,3072] + bias
    sgemm_bias_kernel<<<dim3(N3 / 128, MROWS / 128), 256>>>(
        x, w_qkv, b_qkv, qkv_p, MROWS, N3, DIM);

    // 2) Windowed causal attention
    attn_kernel<<<dim3(16, 512), 256>>>(qkv_p, attn_p);

    // 3) Output projection: [16384,1024] @ [1024,1024] + bias
    sgemm_bias_kernel<<<dim3(DIM / 128, MROWS / 128), 256>>>(
        attn_p, w_o, b_o, out, MROWS, DIM, DIM);
}

// round 3
// speedup vs baseline: 1.7701x; 1.7701x over previous
#include <cuda_runtime.h>
#include <cuda_bf16.h>
#include <math.h>
#include <stdint.h>

// Problem constants (fixed shapes)
#define BV      4
#define SEQ     4096
#define DIM     1024
#define WIN     512
#define HEADS   16
#define DH      64
#define MROWS   (BV * SEQ)     // 16384
#define N3      (3 * DIM)      // 3072
#define NEG_INF_F (-1e9f)

// ---------------------------------------------------------------------------
// Scratch buffers (device globals: sanctioned workaround for no-alloc rule)
// ---------------------------------------------------------------------------
__device__ __nv_bfloat16 g_xhi[(size_t)MROWS * DIM];
__device__ __nv_bfloat16 g_xlo[(size_t)MROWS * DIM];
__device__ __nv_bfloat16 g_wqkvt_hi[(size_t)N3 * DIM];   // W_qkv^T [N3, K]
__device__ __nv_bfloat16 g_wqkvt_lo[(size_t)N3 * DIM];
__device__ __nv_bfloat16 g_wot_hi[(size_t)DIM * DIM];    // W_o^T [N, K]
__device__ __nv_bfloat16 g_wot_lo[(size_t)DIM * DIM];
__device__ float g_qkv[(size_t)MROWS * N3];              // 192 MB fp32
__device__ float g_attn[(size_t)MROWS * DIM];            //  64 MB fp32
__device__ __nv_bfloat16 g_ahi[(size_t)MROWS * DIM];
__device__ __nv_bfloat16 g_alo[(size_t)MROWS * DIM];

// ---------------------------------------------------------------------------
// Helpers (sm_80-portable ISA only: HMMA mma.sync + cp.async)
// ---------------------------------------------------------------------------
__device__ __forceinline__ uint32_t smem_u32(const void* p) {
    uint32_t a;
    asm("{ .reg .u64 t; cvta.to.shared.u64 t, %1; cvt.u32.u64 %0, t; }"
        : "=r"(a) : "l"(p));
    return a;
}
__device__ __forceinline__ uint32_t lds_u32(uint32_t addr) {
    uint32_t v;
    asm volatile("ld.shared.b32 %0, [%1];" : "=r"(v) : "r"(addr));
    return v;
}
#define CP16(dst, src) \
    asm volatile("cp.async.cg.shared.global [%0], [%1], 16;" \
                 :: "r"(dst), "l"(src) : "memory")
#define CP_COMMIT() asm volatile("cp.async.commit_group;" ::: "memory")
#define CP_WAIT1()  asm volatile("cp.async.wait_group 1;" ::: "memory")
#define CP_WAIT0()  asm volatile("cp.async.wait_group 0;" ::: "memory")

__device__ __forceinline__ void mma16816(float* d, const uint32_t* a, const uint32_t* b) {
    asm volatile(
        "mma.sync.aligned.m16n8k16.row.col.f32.bf16.bf16.f32 "
        "{%0,%1,%2,%3}, {%4,%5,%6,%7}, {%8,%9}, {%0,%1,%2,%3};"
        : "+f"(d[0]), "+f"(d[1]), "+f"(d[2]), "+f"(d[3])
        : "r"(a[0]), "r"(a[1]), "r"(a[2]), "r"(a[3]), "r"(b[0]), "r"(b[1]));
}

// Swizzled smem address within a [128 rows x 32B] buffer.
// Physical 16B-chunk = logical chunk XOR ((row>>2)&1) -> conflict-free
// fragment loads (8 rows x 4 lanes hit 32 distinct banks).
__device__ __forceinline__ uint32_t swaddr(uint32_t buf, int row, int byte) {
    return buf + row * 32 + ((((byte >> 4) ^ ((row >> 2) & 1)) << 4) | (byte & 15));
}

// ---------------------------------------------------------------------------
// Split-bf16 HMMA GEMM: C[M,N] = A[M,K] @ B^T + bias   (B stored [N,K])
// 3 products: Ah*Bh + Ah*Bl + Al*Bh  (~1e-5 rel err vs fp32).
// CTA 128x128, 512 threads (16 warps, 32x32 warp tiles), BK=16/stage,
// 3-stage cp.async pipeline, 48KB static smem.
// ---------------------------------------------------------------------------
__global__ __launch_bounds__(512) void gemm_hmma_split(
    const __nv_bfloat16* __restrict__ Ah, const __nv_bfloat16* __restrict__ Al,
    const __nv_bfloat16* __restrict__ Bh, const __nv_bfloat16* __restrict__ Bl,
    const float* __restrict__ bias, float* __restrict__ C,
    int M, int N, int K)
{
    __shared__ char sm[49152];          // 3 stages x (4 bufs x 4KB)
    const uint32_t sb = smem_u32(sm);

    const int tid  = threadIdx.x;
    const int lane = tid & 31, wid = tid >> 5;
    const int g = lane >> 2, tig = lane & 3;
    const int wm = (wid >> 2) * 32;     // warp M offset in CTA tile
    const int wn = (wid & 3) * 32;      // warp N offset
    const int row0 = blockIdx.y * 128, col0 = blockIdx.x * 128;

    // cp.async mapping: thread handles one A-side chunk and one B-side chunk.
    const int lr = (tid & 255) >> 1;    // row 0..127
    const int lc = tid & 1;             // 16B chunk 0/1 within 32B row
    const __nv_bfloat16* gA0 = (tid < 256 ? Ah : Al) + (size_t)(row0 + lr) * K + lc * 8;
    const __nv_bfloat16* gB0 = (tid < 256 ? Bh : Bl) + (size_t)(col0 + lr) * K + lc * 8;
    const uint32_t dstA = sb + (tid >> 8) * 4096 +
                          lr * 32 + ((lc ^ ((lr >> 2) & 1)) << 4);
    const uint32_t dstB = dstA + 8192;

    float acc[2][4][4];
#pragma unroll
    for (int mt = 0; mt < 2; mt++)
#pragma unroll
        for (int nt = 0; nt < 4; nt++)
#pragma unroll
            for (int j = 0; j < 4; j++) acc[mt][nt][j] = 0.f;

    const int nch = K >> 4;             // 64 for K=1024

    // Prologue: stages 0 and 1
    CP16(dstA, gA0);           CP16(dstB, gB0);           CP_COMMIT();
    CP16(dstA + 16384, gA0 + 16); CP16(dstB + 16384, gB0 + 16); CP_COMMIT();

    for (int kc = 0; kc < nch; kc++) {
        if (kc + 1 < nch) { CP_WAIT1(); } else { CP_WAIT0(); }
        __syncthreads();

        const uint32_t st = sb + (kc % 3) * 16384;
        const uint32_t sAh = st, sAl = st + 4096, sBh = st + 8192, sBl = st + 12288;

        uint32_t ah[2][4], al[2][4], bh[4][2], bl[4][2];
#pragma unroll
        for (int mt = 0; mt < 2; mt++) {
            const int r = wm + mt * 16 + g;
            ah[mt][0] = lds_u32(swaddr(sAh, r,     4 * tig));
            ah[mt][1] = lds_u32(swaddr(sAh, r + 8, 4 * tig));
            ah[mt][2] = lds_u32(swaddr(sAh, r,     16 + 4 * tig));
            ah[mt][3] = lds_u32(swaddr(sAh, r + 8, 16 + 4 * tig));
            al[mt][0] = lds_u32(swaddr(sAl, r,     4 * tig));
            al[mt][1] = lds_u32(swaddr(sAl, r + 8, 4 * tig));
            al[mt][2] = lds_u32(swaddr(sAl, r,     16 + 4 * tig));
            al[mt][3] = lds_u32(swaddr(sAl, r + 8, 16 + 4 * tig));
        }
#pragma unroll
        for (int nt = 0; nt < 4; nt++) {
            const int r = wn + nt * 8 + g;
            bh[nt][0] = lds_u32(swaddr(sBh, r, 4 * tig));
            bh[nt][1] = lds_u32(swaddr(sBh, r, 16 + 4 * tig));
            bl[nt][0] = lds_u32(swaddr(sBl, r, 4 * tig));
            bl[nt][1] = lds_u32(swaddr(sBl, r, 16 + 4 * tig));
        }
#pragma unroll
        for (int mt = 0; mt < 2; mt++)
#pragma unroll
            for (int nt = 0; nt < 4; nt++) {
                mma16816(acc[mt][nt], ah[mt], bh[nt]);
                mma16816(acc[mt][nt], ah[mt], bl[nt]);
                mma16816(acc[mt][nt], al[mt], bh[nt]);
            }
        __syncthreads();

        if (kc + 2 < nch) {
            const uint32_t so = ((kc + 2) % 3) * 16384;
            const int ko = (kc + 2) * 16;
            CP16(dstA + so, gA0 + ko);
            CP16(dstB + so, gB0 + ko);
            CP_COMMIT();
        }
    }

    // Epilogue: c0/c1 -> (row, col..col+1), c2/c3 -> (row+8, ...)
#pragma unroll
    for (int mt = 0; mt < 2; mt++) {
        const int r = row0 + wm + mt * 16 + g;
#pragma unroll
        for (int nt = 0; nt < 4; nt++) {
            const int c = col0 + wn + nt * 8 + tig * 2;
            const float bx = bias[c], by = bias[c + 1];
            float2 v0 = { acc[mt][nt][0] + bx, acc[mt][nt][1] + by };
            float2 v1 = { acc[mt][nt][2] + bx, acc[mt][nt][3] + by };
            *(float2*)&C[(size_t)r * N + c]       = v0;
            *(float2*)&C[(size_t)(r + 8) * N + c] = v1;
        }
    }
}

// ---------------------------------------------------------------------------
// fp32 -> bf16 hi/lo split (elementwise, vectorized by 4)
// ---------------------------------------------------------------------------
__global__ __launch_bounds__(256) void split_kernel(
    const float4* __restrict__ in, __nv_bfloat16* __restrict__ hi,
    __nv_bfloat16* __restrict__ lo, int n4)
{
    int i = blockIdx.x * 256 + threadIdx.x;
    if (i >= n4) return;
    float4 v = in[i];
    float xs[4] = { v.x, v.y, v.z, v.w };
    __nv_bfloat16 hs[4], ls[4];
#pragma unroll
    for (int j = 0; j < 4; j++) {
        hs[j] = __float2bfloat16(xs[j]);
        ls[j] = __float2bfloat16(xs[j] - __bfloat162float(hs[j]));
    }
    ((__nv_bfloat162*)hi)[2 * i + 0] = __nv_bfloat162(hs[0], hs[1]);
    ((__nv_bfloat162*)hi)[2 * i + 1] = __nv_bfloat162(hs[2], hs[3]);
    ((__nv_bfloat162*)lo)[2 * i + 0] = __nv_bfloat162(ls[0], ls[1]);
    ((__nv_bfloat162*)lo)[2 * i + 1] = __nv_bfloat162(ls[2], ls[3]);
}

// ---------------------------------------------------------------------------
// Transpose + split: W [K, N] fp32 -> Wt_hi/Wt_lo [N, K] bf16
// ---------------------------------------------------------------------------
__global__ __launch_bounds__(256) void tsplit_kernel(
    const float* __restrict__ W, __nv_bfloat16* __restrict__ Th,
    __nv_bfloat16* __restrict__ Tl, int K, int N)
{
    __shared__ float t[32][33];
    const int nb = blockIdx.x * 32, kb = blockIdx.y * 32;
    const int tx = threadIdx.x, ty = threadIdx.y;
    for (int y = ty; y < 32; y += 8)
        t[y][tx] = W[(size_t)(kb + y) * N + nb + tx];
    __syncthreads();
    for (int y = ty; y < 32; y += 8) {
        float v = t[tx][y];   // = W[kb+tx][nb+y]
        __nv_bfloat16 h = __float2bfloat16(v);
        __nv_bfloat16 l = __float2bfloat16(v - __bfloat162float(h));
        size_t o = (size_t)(nb + y) * K + kb + tx;
        Th[o] = h;
        Tl[o] = l;
    }
}

// ---------------------------------------------------------------------------
// Windowed causal attention (flash-style, fp32) — unchanged (passing)
// ---------------------------------------------------------------------------
__global__ __launch_bounds__(256) void attn_kernel(
    const float* __restrict__ qkv, float* __restrict__ outp)
{
    const int qt   = blockIdx.x;
    const int pair = blockIdx.y;
    const int bn   = pair >> 4;
    const int h    = pair & 15;
    const int tid  = threadIdx.x;
    const int tx   = tid & 15;
    const int ty   = tid >> 4;
    const int mbase = bn * WIN;
    const int qcol  = h * DH;

    __shared__ float Qs[32 * 65];
    __shared__ float KPs[64 * 65];
    __shared__ float Vs[64 * 64];

    for (int idx = tid; idx < 32 * 64; idx += 256) {
        int r = idx >> 6, c = idx & 63;
        Qs[r * 65 + c] = qkv[(size_t)(mbase + qt * 32 + r) * N3 + qcol + c];
    }

    float m_i[2] = { -INFINITY, -INFINITY };
    float l_i[2] = { 0.f, 0.f };
    float o_acc[2][4] = {};

    const int gq0 = qt * 32 + ty * 2;
    const int ktmax = (qt * 32 + 31) >> 6;
    __syncthreads();

    for (int kt = 0; kt <= ktmax; kt++) {
        for (int idx = tid; idx < 64 * 64; idx += 256) {
            int r = idx >> 6, c = idx & 63;
            size_t gg = (size_t)(mbase + kt * 64 + r) * N3 + qcol + c;
            KPs[r * 65 + c] = qkv[gg + DIM];
            Vs[idx]         = qkv[gg + 2 * DIM];
        }
        __syncthreads();

        float s[2][4];
#pragma unroll
        for (int i = 0; i < 2; i++)
#pragma unroll
            for (int j = 0; j < 4; j++) s[i][j] = 0.f;

#pragma unroll 8
        for (int d = 0; d < 64; d++) {
            float ra0 = Qs[(ty * 2 + 0) * 65 + d];
            float ra1 = Qs[(ty * 2 + 1) * 65 + d];
#pragma unroll
            for (int j = 0; j < 4; j++) {
                float rb = KPs[(tx * 4 + j) * 65 + d];
                s[0][j] += ra0 * rb;
                s[1][j] += ra1 * rb;
            }
        }
        __syncthreads();

#pragma unroll
        for (int i = 0; i < 2; i++) {
            const int gq = gq0 + i;
#pragma unroll
            for (int j = 0; j < 4; j++) {
                int gk = kt * 64 + tx * 4 + j;
                float v = s[i][j] * 0.125f;
                s[i][j] = (gk > gq) ? NEG_INF_F : v;
            }
            float rm = fmaxf(fmaxf(s[i][0], s[i][1]), fmaxf(s[i][2], s[i][3]));
#pragma unroll
            for (int o = 1; o < 16; o <<= 1)
                rm = fmaxf(rm, __shfl_xor_sync(0xffffffffu, rm, o));
            float mn   = fmaxf(m_i[i], rm);
            float corr = __expf(m_i[i] - mn);
            float rs = 0.f;
#pragma unroll
            for (int j = 0; j < 4; j++) {
                float p = __expf(s[i][j] - mn);
                s[i][j] = p;
                rs += p;
            }
#pragma unroll
            for (int o = 1; o < 16; o <<= 1)
                rs += __shfl_xor_sync(0xffffffffu, rs, o);
            l_i[i] = l_i[i] * corr + rs;
            m_i[i] = mn;
#pragma unroll
            for (int j = 0; j < 4; j++) o_acc[i][j] *= corr;
#pragma unroll
            for (int j = 0; j < 4; j++)
                KPs[(ty * 2 + i) * 65 + tx * 4 + j] = s[i][j];
        }
        __syncthreads();

#pragma unroll 8
        for (int k = 0; k < 64; k++) {
            float ra0 = KPs[(ty * 2 + 0) * 65 + k];
            float ra1 = KPs[(ty * 2 + 1) * 65 + k];
            float4 rb = *(const float4*)&Vs[k * 64 + tx * 4];
            o_acc[0][0] += ra0 * rb.x; o_acc[0][1] += ra0 * rb.y;
            o_acc[0][2] += ra0 * rb.z; o_acc[0][3] += ra0 * rb.w;
            o_acc[1][0] += ra1 * rb.x; o_acc[1][1] += ra1 * rb.y;
            o_acc[1][2] += ra1 * rb.z; o_acc[1][3] += ra1 * rb.w;
        }
        __syncthreads();
    }

#pragma unroll
    for (int i = 0; i < 2; i++) {
        float inv = 1.f / l_i[i];
        size_t r = (size_t)(mbase + qt * 32 + ty * 2 + i);
#pragma unroll
        for (int j = 0; j < 4; j++)
            outp[r * DIM + qcol + tx * 4 + j] = o_acc[i][j] * inv;
    }
}

// ---------------------------------------------------------------------------
extern "C" void kernel_launch(void* const* d_in, const int* in_sizes, int n_in,
                              void* d_out, int out_size)
{
    (void)in_sizes; (void)n_in; (void)out_size;
    const float* x     = (const float*)d_in[0];
    const float* w_qkv = (const float*)d_in[1];
    const float* b_qkv = (const float*)d_in[2];
    const float* w_o   = (const float*)d_in[3];
    const float* b_o   = (const float*)d_in[4];
    float* out = (float*)d_out;

    __nv_bfloat16 *xhi, *xlo, *wqt_h, *wqt_l, *wot_h, *wot_l, *ahi, *alo;
    float *qkv_p, *attn_p;
    cudaGetSymbolAddress((void**)&xhi,   g_xhi);
    cudaGetSymbolAddress((void**)&xlo,   g_xlo);
    cudaGetSymbolAddress((void**)&wqt_h, g_wqkvt_hi);
    cudaGetSymbolAddress((void**)&wqt_l, g_wqkvt_lo);
    cudaGetSymbolAddress((void**)&wot_h, g_wot_hi);
    cudaGetSymbolAddress((void**)&wot_l, g_wot_lo);
    cudaGetSymbolAddress((void**)&ahi,   g_ahi);
    cudaGetSymbolAddress((void**)&alo,   g_alo);
    cudaGetSymbolAddress((void**)&qkv_p, g_qkv);
    cudaGetSymbolAddress((void**)&attn_p, g_attn);

    // 1) Split x into bf16 hi/lo
    {
        int n4 = MROWS * DIM / 4;
        split_kernel<<<n4 / 256, 256>>>((const float4*)x, xhi, xlo, n4);
    }
    // 2) Transpose + split weights
    tsplit_kernel<<<dim3(N3 / 32, DIM / 32), dim3(32, 8)>>>(w_qkv, wqt_h, wqt_l, DIM, N3);
    tsplit_kernel<<<dim3(DIM / 32, DIM / 32), dim3(32, 8)>>>(w_o, wot_h, wot_l, DIM, DIM);

    // 3) QKV projection on tensor cores (HMMA split-bf16)
    gemm_hmma_split<<<dim3(N3 / 128, MROWS / 128), 512>>>(
        xhi, xlo, wqt_h, wqt_l, b_qkv, qkv_p, MROWS, N3, DIM);

    // 4) Windowed causal attention (fp32)
    attn_kernel<<<dim3(16, 512), 256>>>(qkv_p, attn_p);

    // 5) Split attention output
    {
        int n4 = MROWS * DIM / 4;
        split_kernel<<<n4 / 256, 256>>>((const float4*)attn_p, ahi, alo, n4);
    }
    // 6) Output projection on tensor cores
    gemm_hmma_split<<<dim3(DIM / 128, MROWS / 128), 512>>>(
        ahi, alo, wot_h, wot_l, b_o, out, MROWS, DIM, DIM);
}

// round 4
// speedup vs baseline: 2.3135x; 1.3070x over previous
#include <cuda_runtime.h>
#include <cuda_bf16.h>
#include <math.h>
#include <stdint.h>

// Problem constants (fixed shapes)
#define BV      4
#define SEQ     4096
#define DIM     1024
#define WIN     512
#define HEADS   16
#define DH      64
#define MROWS   (BV * SEQ)     // 16384
#define N3      (3 * DIM)      // 3072
#define NEG_INF_F (-1e9f)

// ---------------------------------------------------------------------------
// Scratch (device globals: sanctioned workaround for the no-alloc rule)
// ---------------------------------------------------------------------------
__device__ __nv_bfloat16 g_xhi[(size_t)MROWS * DIM];
__device__ __nv_bfloat16 g_xlo[(size_t)MROWS * DIM];
__device__ __nv_bfloat16 g_wqkvt_hi[(size_t)N3 * DIM];   // W_qkv^T [N3, K]
__device__ __nv_bfloat16 g_wqkvt_lo[(size_t)N3 * DIM];
__device__ __nv_bfloat16 g_wot_hi[(size_t)DIM * DIM];    // W_o^T  [N, K]
__device__ __nv_bfloat16 g_wot_lo[(size_t)DIM * DIM];
__device__ __nv_bfloat16 g_qkvh[(size_t)MROWS * N3];     // 96 MB
__device__ __nv_bfloat16 g_qkvl[(size_t)MROWS * N3];     // 96 MB
__device__ __nv_bfloat16 g_ahi[(size_t)MROWS * DIM];
__device__ __nv_bfloat16 g_alo[(size_t)MROWS * DIM];

// ---------------------------------------------------------------------------
// Helpers (sm_80-portable ISA: mma.sync + cp.async + ldmatrix)
// ---------------------------------------------------------------------------
__device__ __forceinline__ uint32_t smem_u32(const void* p) {
    uint32_t a;
    asm("{ .reg .u64 t; cvta.to.shared.u64 t, %1; cvt.u32.u64 %0, t; }"
        : "=r"(a) : "l"(p));
    return a;
}
#define CP16(dst, src) \
    asm volatile("cp.async.cg.shared.global [%0], [%1], 16;" \
                 :: "r"(dst), "l"(src) : "memory")
#define CP_COMMIT() asm volatile("cp.async.commit_group;" ::: "memory")
#define CP_WAIT1()  asm volatile("cp.async.wait_group 1;" ::: "memory")
#define CP_WAIT0()  asm volatile("cp.async.wait_group 0;" ::: "memory")

#define LDSM_X4(r0, r1, r2, r3, a) \
    asm volatile("ldmatrix.sync.aligned.m8n8.x4.shared.b16 {%0,%1,%2,%3}, [%4];" \
                 : "=r"(r0), "=r"(r1), "=r"(r2), "=r"(r3) : "r"(a))
#define LDSM_X4T(r0, r1, r2, r3, a) \
    asm volatile("ldmatrix.sync.aligned.m8n8.x4.trans.shared.b16 {%0,%1,%2,%3}, [%4];" \
                 : "=r"(r0), "=r"(r1), "=r"(r2), "=r"(r3) : "r"(a))

__device__ __forceinline__ void mma16816(float* d, const uint32_t* a, const uint32_t* b) {
    asm volatile(
        "mma.sync.aligned.m16n8k16.row.col.f32.bf16.bf16.f32 "
        "{%0,%1,%2,%3}, {%4,%5,%6,%7}, {%8,%9}, {%0,%1,%2,%3};"
        : "+f"(d[0]), "+f"(d[1]), "+f"(d[2]), "+f"(d[3])
        : "r"(a[0]), "r"(a[1]), "r"(a[2]), "r"(a[3]), "r"(b[0]), "r"(b[1]));
}

__device__ __forceinline__ uint32_t packbf2(float a, float b) {
    __nv_bfloat162 t(__float2bfloat16(a), __float2bfloat16(b));
    return *reinterpret_cast<uint32_t*>(&t);
}

// ---------------------------------------------------------------------------
// Split-bf16 HMMA GEMM: C[M,N] = A[M,K] @ B^T + bias   (B stored [N,K])
// 3 products: Ah*Bh + Ah*Bl + Al*Bh.
// CTA 128x128, 512 threads (16 warps, 32x32 warp tiles), BK=16/stage,
// 3-stage cp.async pipeline, ldmatrix fragment loads, 1 barrier/chunk.
// SPLIT=0: fp32 C + bias.  SPLIT=1: bf16 hi/lo outputs + bias.
// Smem rows are 32B (2 x 16B chunks), phys chunk = chunk ^ ((row>>2)&1).
// ---------------------------------------------------------------------------
template<int SPLIT>
__global__ __launch_bounds__(512) void gemm_hmma(
    const __nv_bfloat16* __restrict__ Ah, const __nv_bfloat16* __restrict__ Al,
    const __nv_bfloat16* __restrict__ Bh, const __nv_bfloat16* __restrict__ Bl,
    const float* __restrict__ bias, float* __restrict__ C,
    __nv_bfloat16* __restrict__ Ch, __nv_bfloat16* __restrict__ Cl,
    int M, int N, int K)
{
    __shared__ char sm[49152];          // 3 stages x (4 bufs x 4KB)
    const uint32_t sb = smem_u32(sm);

    const int tid  = threadIdx.x;
    const int lane = tid & 31, wid = tid >> 5;
    const int g = lane >> 2, tig = lane & 3;
    const int jj = lane & 7, grp = lane >> 3;
    const int wm = (wid >> 2) * 32;
    const int wn = (wid & 3) * 32;
    const int row0 = blockIdx.y * 128, col0 = blockIdx.x * 128;

    // cp.async mapping (as validated in R3)
    const int lr = (tid & 255) >> 1;
    const int lc = tid & 1;
    const __nv_bfloat16* gA0 = (tid < 256 ? Ah : Al) + (size_t)(row0 + lr) * K + lc * 8;
    const __nv_bfloat16* gB0 = (tid < 256 ? Bh : Bl) + (size_t)(col0 + lr) * K + lc * 8;
    const uint32_t dstA = sb + (tid >> 8) * 4096 +
                          lr * 32 + ((lc ^ ((lr >> 2) & 1)) << 4);
    const uint32_t dstB = dstA + 8192;

    // ldmatrix per-lane relative offsets (stage-invariant)
    uint32_t aoff[2], boff[2];
#pragma unroll
    for (int mt = 0; mt < 2; mt++) {
        int r = wm + mt * 16 + (grp & 1) * 8 + jj;
        int c = grp >> 1;
        aoff[mt] = r * 32 + ((c ^ ((r >> 2) & 1)) << 4);
    }
#pragma unroll
    for (int pr = 0; pr < 2; pr++) {
        int r = wn + pr * 16 + (grp >> 1) * 8 + jj;
        int c = grp & 1;
        boff[pr] = r * 32 + ((c ^ ((r >> 2) & 1)) << 4);
    }

    float acc[2][4][4];
#pragma unroll
    for (int mt = 0; mt < 2; mt++)
#pragma unroll
        for (int nt = 0; nt < 4; nt++)
#pragma unroll
            for (int j = 0; j < 4; j++) acc[mt][nt][j] = 0.f;

    const int nch = K >> 4;

    CP16(dstA, gA0);              CP16(dstB, gB0);              CP_COMMIT();
    CP16(dstA + 16384, gA0 + 16); CP16(dstB + 16384, gB0 + 16); CP_COMMIT();

    for (int kc = 0; kc < nch; kc++) {
        if (kc + 1 < nch) { CP_WAIT1(); } else { CP_WAIT0(); }
        __syncthreads();
        if (kc + 2 < nch) {
            const uint32_t so = ((kc + 2) % 3) * 16384;
            const int ko = (kc + 2) * 16;
            CP16(dstA + so, gA0 + ko);
            CP16(dstB + so, gB0 + ko);
            CP_COMMIT();
        }

        const uint32_t st = sb + (kc % 3) * 16384;
        uint32_t ah[2][4], al[2][4], bh[4][2], bl[4][2];
        LDSM_X4(ah[0][0], ah[0][1], ah[0][2], ah[0][3], st + aoff[0]);
        LDSM_X4(ah[1][0], ah[1][1], ah[1][2], ah[1][3], st + aoff[1]);
        LDSM_X4(al[0][0], al[0][1], al[0][2], al[0][3], st + 4096 + aoff[0]);
        LDSM_X4(al[1][0], al[1][1], al[1][2], al[1][3], st + 4096 + aoff[1]);
        LDSM_X4(bh[0][0], bh[0][1], bh[1][0], bh[1][1], st + 8192 + boff[0]);
        LDSM_X4(bh[2][0], bh[2][1], bh[3][0], bh[3][1], st + 8192 + boff[1]);
        LDSM_X4(bl[0][0], bl[0][1], bl[1][0], bl[1][1], st + 12288 + boff[0]);
        LDSM_X4(bl[2][0], bl[2][1], bl[3][0], bl[3][1], st + 12288 + boff[1]);

#pragma unroll
        for (int mt = 0; mt < 2; mt++)
#pragma unroll
            for (int nt = 0; nt < 4; nt++) {
                mma16816(acc[mt][nt], ah[mt], bh[nt]);
                mma16816(acc[mt][nt], ah[mt], bl[nt]);
                mma16816(acc[mt][nt], al[mt], bh[nt]);
            }
    }

#pragma unroll
    for (int mt = 0; mt < 2; mt++) {
        const int r = row0 + wm + mt * 16 + g;
#pragma unroll
        for (int nt = 0; nt < 4; nt++) {
            const int c = col0 + wn + nt * 8 + tig * 2;
            const float bx = bias[c], by = bias[c + 1];
            float v00 = acc[mt][nt][0] + bx, v01 = acc[mt][nt][1] + by;
            float v10 = acc[mt][nt][2] + bx, v11 = acc[mt][nt][3] + by;
            if (SPLIT) {
                __nv_bfloat16 h00 = __float2bfloat16(v00), h01 = __float2bfloat16(v01);
                __nv_bfloat16 h10 = __float2bfloat16(v10), h11 = __float2bfloat16(v11);
                __nv_bfloat162 l0(__float2bfloat16(v00 - __bfloat162float(h00)),
                                  __float2bfloat16(v01 - __bfloat162float(h01)));
                __nv_bfloat162 l1(__float2bfloat16(v10 - __bfloat162float(h10)),
                                  __float2bfloat16(v11 - __bfloat162float(h11)));
                *(__nv_bfloat162*)&Ch[(size_t)r * N + c]       = __nv_bfloat162(h00, h01);
                *(__nv_bfloat162*)&Ch[(size_t)(r + 8) * N + c] = __nv_bfloat162(h10, h11);
                *(__nv_bfloat162*)&Cl[(size_t)r * N + c]       = l0;
                *(__nv_bfloat162*)&Cl[(size_t)(r + 8) * N + c] = l1;
            } else {
                float2 a0 = { v00, v01 }, a1 = { v10, v11 };
                *(float2*)&C[(size_t)r * N + c]       = a0;
                *(float2*)&C[(size_t)(r + 8) * N + c] = a1;
            }
        }
    }
}

// ---------------------------------------------------------------------------
// fp32 -> bf16 hi/lo split (elementwise)
// ---------------------------------------------------------------------------
__global__ __launch_bounds__(256) void split_kernel(
    const float4* __restrict__ in, __nv_bfloat16* __restrict__ hi,
    __nv_bfloat16* __restrict__ lo, int n4)
{
    int i = blockIdx.x * 256 + threadIdx.x;
    if (i >= n4) return;
    float4 v = in[i];
    float xs[4] = { v.x, v.y, v.z, v.w };
    __nv_bfloat16 hs[4], ls[4];
#pragma unroll
    for (int j = 0; j < 4; j++) {
        hs[j] = __float2bfloat16(xs[j]);
        ls[j] = __float2bfloat16(xs[j] - __bfloat162float(hs[j]));
    }
    ((__nv_bfloat162*)hi)[2 * i + 0] = __nv_bfloat162(hs[0], hs[1]);
    ((__nv_bfloat162*)hi)[2 * i + 1] = __nv_bfloat162(hs[2], hs[3]);
    ((__nv_bfloat162*)lo)[2 * i + 0] = __nv_bfloat162(ls[0], ls[1]);
    ((__nv_bfloat162*)lo)[2 * i + 1] = __nv_bfloat162(ls[2], ls[3]);
}

// ---------------------------------------------------------------------------
// Transpose + split: W [K, N] fp32 -> Wt_hi/Wt_lo [N, K] bf16
// ---------------------------------------------------------------------------
__global__ __launch_bounds__(256) void tsplit_kernel(
    const float* __restrict__ W, __nv_bfloat16* __restrict__ Th,
    __nv_bfloat16* __restrict__ Tl, int K, int N)
{
    __shared__ float t[32][33];
    const int nb = blockIdx.x * 32, kb = blockIdx.y * 32;
    const int tx = threadIdx.x, ty = threadIdx.y;
    for (int y = ty; y < 32; y += 8)
        t[y][tx] = W[(size_t)(kb + y) * N + nb + tx];
    __syncthreads();
    for (int y = ty; y < 32; y += 8) {
        float v = t[tx][y];
        __nv_bfloat16 h = __float2bfloat16(v);
        __nv_bfloat16 l = __float2bfloat16(v - __bfloat162float(h));
        size_t o = (size_t)(nb + y) * K + kb + tx;
        Th[o] = h;
        Tl[o] = l;
    }
}

// ---------------------------------------------------------------------------
// Windowed causal attention, split-bf16 HMMA flash kernel.
// Block: 128 threads (4 warps). Grid: (8 q-tiles of 64 rows, 32 win x 16 heads).
// Per warp: 16 q rows. KV tiles of 32 rows, 2-stage cp.async pipeline.
// Smem (48KB): Qh 8K | Ql 8K | stage{0,1}: Kh 4K, Kl 4K, Vh 4K, Vl 4K.
// Tile rows are 128B (8 x 16B chunks); phys chunk = chunk ^ (row & 7).
// ---------------------------------------------------------------------------
__device__ __forceinline__ void attn_load_kv(
    uint32_t sstage, const __nv_bfloat16* qh_g, const __nv_bfloat16* ql_g,
    size_t rowbase, int tid)
{
#pragma unroll
    for (int it = 0; it < 8; it++) {
        int i = tid + it * 128;
        int buf = i >> 8, within = i & 255;
        int r = within >> 3, c = within & 7;
        uint32_t dst = sstage + buf * 4096 + r * 128 + ((c ^ (r & 7)) << 4);
        size_t go = rowbase + (size_t)r * N3 + c * 8;
        const __nv_bfloat16* src;
        if (buf == 0)      src = qh_g + go + DIM;       // Kh
        else if (buf == 1) src = ql_g + go + DIM;       // Kl
        else if (buf == 2) src = qh_g + go + 2 * DIM;   // Vh
        else               src = ql_g + go + 2 * DIM;   // Vl
        CP16(dst, src);
    }
}

__global__ __launch_bounds__(128) void attn_hmma(
    const __nv_bfloat16* __restrict__ qh_g, const __nv_bfloat16* __restrict__ ql_g,
    __nv_bfloat16* __restrict__ ohi, __nv_bfloat16* __restrict__ olo)
{
    const int qt  = blockIdx.x;          // 0..7
    const int wh  = blockIdx.y;          // 0..511
    const int win = wh >> 4, h = wh & 15;
    const int mbase = win * WIN;
    const int qcol  = h * DH;
    const int tid = threadIdx.x, lane = tid & 31, w = tid >> 5;
    const int g = lane >> 2, tig = lane & 3;
    const int jj = lane & 7, grp = lane >> 3;

    __shared__ char sm[49152];
    const uint32_t sb = smem_u32(sm);

    // Load Q tile [64 x 64] hi/lo (plain vectorized stores, swizzled)
    for (int i = tid; i < 512; i += 128) {
        int r = i >> 3, c = i & 7;
        uint32_t off = r * 128 + ((c ^ (r & 7)) << 4);
        size_t gsrc = (size_t)(mbase + qt * 64 + r) * N3 + qcol + c * 8;
        *(uint4*)(sm + off)        = *(const uint4*)(qh_g + gsrc);
        *(uint4*)(sm + 8192 + off) = *(const uint4*)(ql_g + gsrc);
    }

    const int ktmax = 2 * qt + 1;
    attn_load_kv(sb + 16384, qh_g, ql_g,
                 (size_t)mbase * N3 + qcol, tid);
    CP_COMMIT();
    __syncthreads();     // Q visible to all warps

    // Q fragments (held in registers for the whole block)
    uint32_t qfh[4][4], qfl[4][4];
    const int qrow = w * 16 + (grp & 1) * 8 + jj;
#pragma unroll
    for (int kk = 0; kk < 4; kk++) {
        int c = 2 * kk + (grp >> 1);
        uint32_t off = qrow * 128 + ((c ^ (qrow & 7)) << 4);
        LDSM_X4(qfh[kk][0], qfh[kk][1], qfh[kk][2], qfh[kk][3], sb + off);
        LDSM_X4(qfl[kk][0], qfl[kk][1], qfl[kk][2], qfl[kk][3], sb + 8192 + off);
    }

    float m0 = -INFINITY, m1 = -INFINITY, l0 = 0.f, l1 = 0.f;
    float oacc[8][4];
#pragma unroll
    for (int nt = 0; nt < 8; nt++)
#pragma unroll
        for (int j = 0; j < 4; j++) oacc[nt][j] = 0.f;

    const int gq0 = qt * 64 + w * 16 + g;
    const int gq1 = gq0 + 8;
    const int krowb = (grp >> 1) * 8 + jj;       // K-frag row (add pair*16)
    const int vrow0 = (grp & 1) * 8 + jj;        // V-frag row (add kk2*16)

    for (int kt = 0; kt <= ktmax; kt++) {
        CP_WAIT0();
        __syncthreads();
        if (kt < ktmax)
            attn_load_kv(sb + 16384 + ((kt + 1) & 1) * 16384, qh_g, ql_g,
                         (size_t)(mbase + (kt + 1) * 32) * N3 + qcol, tid);
        if (kt < ktmax) CP_COMMIT();

        const uint32_t stg = sb + 16384 + (kt & 1) * 16384;

        // ---- S = Q K^T (split, 3 products) ----
        float sacc[4][4];
#pragma unroll
        for (int nt = 0; nt < 4; nt++)
#pragma unroll
            for (int j = 0; j < 4; j++) sacc[nt][j] = 0.f;

#pragma unroll
        for (int kk = 0; kk < 4; kk++) {
            uint32_t kbh[4][2], kbl[4][2];
#pragma unroll
            for (int pr = 0; pr < 2; pr++) {
                int r = pr * 16 + krowb;
                int c = 2 * kk + (grp & 1);
                uint32_t off = r * 128 + ((c ^ (r & 7)) << 4);
                LDSM_X4(kbh[pr*2][0], kbh[pr*2][1], kbh[pr*2+1][0], kbh[pr*2+1][1],
                        stg + off);
                LDSM_X4(kbl[pr*2][0], kbl[pr*2][1], kbl[pr*2+1][0], kbl[pr*2+1][1],
                        stg + 4096 + off);
            }
#pragma unroll
            for (int nt = 0; nt < 4; nt++) {
                mma16816(sacc[nt], qfh[kk], kbh[nt]);
                mma16816(sacc[nt], qfh[kk], kbl[nt]);
                mma16816(sacc[nt], qfl[kk], kbh[nt]);
            }
        }

        // ---- scale + causal mask ----
#pragma unroll
        for (int nt = 0; nt < 4; nt++) {
            int colb = kt * 32 + nt * 8 + 2 * tig;
            sacc[nt][0] = (colb     > gq0) ? NEG_INF_F : sacc[nt][0] * 0.125f;
            sacc[nt][1] = (colb + 1 > gq0) ? NEG_INF_F : sacc[nt][1] * 0.125f;
            sacc[nt][2] = (colb     > gq1) ? NEG_INF_F : sacc[nt][2] * 0.125f;
            sacc[nt][3] = (colb + 1 > gq1) ? NEG_INF_F : sacc[nt][3] * 0.125f;
        }

        // ---- online softmax (rows g, g+8; reduce over tig lanes) ----
        float rm0 = fmaxf(fmaxf(sacc[0][0], sacc[0][1]), fmaxf(sacc[1][0], sacc[1][1]));
        rm0 = fmaxf(rm0, fmaxf(fmaxf(sacc[2][0], sacc[2][1]), fmaxf(sacc[3][0], sacc[3][1])));
        float rm1 = fmaxf(fmaxf(sacc[0][2], sacc[0][3]), fmaxf(sacc[1][2], sacc[1][3]));
        rm1 = fmaxf(rm1, fmaxf(fmaxf(sacc[2][2], sacc[2][3]), fmaxf(sacc[3][2], sacc[3][3])));
        rm0 = fmaxf(rm0, __shfl_xor_sync(0xffffffffu, rm0, 1));
        rm0 = fmaxf(rm0, __shfl_xor_sync(0xffffffffu, rm0, 2));
        rm1 = fmaxf(rm1, __shfl_xor_sync(0xffffffffu, rm1, 1));
        rm1 = fmaxf(rm1, __shfl_xor_sync(0xffffffffu, rm1, 2));

        float mn0 = fmaxf(m0, rm0), mn1 = fmaxf(m1, rm1);
        float corr0 = __expf(m0 - mn0), corr1 = __expf(m1 - mn1);
        m0 = mn0; m1 = mn1;

        float rs0 = 0.f, rs1 = 0.f;
#pragma unroll
        for (int nt = 0; nt < 4; nt++) {
            sacc[nt][0] = __expf(sacc[nt][0] - mn0);
            sacc[nt][1] = __expf(sacc[nt][1] - mn0);
            sacc[nt][2] = __expf(sacc[nt][2] - mn1);
            sacc[nt][3] = __expf(sacc[nt][3] - mn1);
            rs0 += sacc[nt][0] + sacc[nt][1];
            rs1 += sacc[nt][2] + sacc[nt][3];
        }
        rs0 += __shfl_xor_sync(0xffffffffu, rs0, 1);
        rs0 += __shfl_xor_sync(0xffffffffu, rs0, 2);
        rs1 += __shfl_xor_sync(0xffffffffu, rs1, 1);
        rs1 += __shfl_xor_sync(0xffffffffu, rs1, 2);
        l0 = l0 * corr0 + rs0;
        l1 = l1 * corr1 + rs1;

#pragma unroll
        for (int nt = 0; nt < 8; nt++) {
            oacc[nt][0] *= corr0; oacc[nt][1] *= corr0;
            oacc[nt][2] *= corr1; oacc[nt][3] *= corr1;
        }

        // ---- P fragments (FA2 identity: C-frag == A-frag layout) ----
        uint32_t pah[2][4], pal[2][4];
#pragma unroll
        for (int kk2 = 0; kk2 < 2; kk2++) {
            int a = 2 * kk2, b = a + 1;
            pah[kk2][0] = packbf2(sacc[a][0], sacc[a][1]);
            pah[kk2][1] = packbf2(sacc[a][2], sacc[a][3]);
            pah[kk2][2] = packbf2(sacc[b][0], sacc[b][1]);
            pah[kk2][3] = packbf2(sacc[b][2], sacc[b][3]);
            __nv_bfloat162* t;
            t = (__nv_bfloat162*)&pah[kk2][0];
            pal[kk2][0] = packbf2(sacc[a][0] - __bfloat162float(t->x),
                                  sacc[a][1] - __bfloat162float(t->y));
            t = (__nv_bfloat162*)&pah[kk2][1];
            pal[kk2][1] = packbf2(sacc[a][2] - __bfloat162float(t->x),
                                  sacc[a][3] - __bfloat162float(t->y));
            t = (__nv_bfloat162*)&pah[kk2][2];
            pal[kk2][2] = packbf2(sacc[b][0] - __bfloat162float(t->x),
                                  sacc[b][1] - __bfloat162float(t->y));
            t = (__nv_bfloat162*)&pah[kk2][3];
            pal[kk2][3] = packbf2(sacc[b][2] - __bfloat162float(t->x),
                                  sacc[b][3] - __bfloat162float(t->y));
        }

        // ---- O += P V (split, 3 products); V via ldmatrix.trans ----
#pragma unroll
        for (int kk2 = 0; kk2 < 2; kk2++) {
            int r = kk2 * 16 + vrow0;
#pragma unroll
            for (int pr = 0; pr < 4; pr++) {
                int c = pr * 2 + (grp >> 1);
                uint32_t off = r * 128 + ((c ^ (r & 7)) << 4);
                uint32_t vh0[2], vh1[2], vl0[2], vl1[2];
                LDSM_X4T(vh0[0], vh0[1], vh1[0], vh1[1], stg + 8192 + off);
                LDSM_X4T(vl0[0], vl0[1], vl1[0], vl1[1], stg + 12288 + off);
                mma16816(oacc[pr*2],   pah[kk2], vh0);
                mma16816(oacc[pr*2],   pal[kk2], vh0);
                mma16816(oacc[pr*2],   pah[kk2], vl0);
                mma16816(oacc[pr*2+1], pah[kk2], vh1);
                mma16816(oacc[pr*2+1], pal[kk2], vh1);
                mma16816(oacc[pr*2+1], pah[kk2], vl1);
            }
        }
    }

    // ---- epilogue: normalize + split-bf16 store ----
    const float inv0 = 1.f / l0, inv1 = 1.f / l1;
    const size_t r0 = (size_t)(mbase + qt * 64 + w * 16 + g);
    const size_t r1 = r0 + 8;
#pragma unroll
    for (int nt = 0; nt < 8; nt++) {
        int c = qcol + nt * 8 + tig * 2;
        float v00 = oacc[nt][0] * inv0, v01 = oacc[nt][1] * inv0;
        float v10 = oacc[nt][2] * inv1, v11 = oacc[nt][3] * inv1;
        __nv_bfloat16 h00 = __float2bfloat16(v00), h01 = __float2bfloat16(v01);
        __nv_bfloat16 h10 = __float2bfloat16(v10), h11 = __float2bfloat16(v11);
        *(__nv_bfloat162*)&ohi[r0 * DIM + c] = __nv_bfloat162(h00, h01);
        *(__nv_bfloat162*)&ohi[r1 * DIM + c] = __nv_bfloat162(h10, h11);
        *(__nv_bfloat162*)&olo[r0 * DIM + c] =
            __nv_bfloat162(__float2bfloat16(v00 - __bfloat162float(h00)),
                           __float2bfloat16(v01 - __bfloat162float(h01)));
        *(__nv_bfloat162*)&olo[r1 * DIM + c] =
            __nv_bfloat162(__float2bfloat16(v10 - __bfloat162float(h10)),
                           __float2bfloat16(v11 - __bfloat162float(h11)));
    }
}

// ---------------------------------------------------------------------------
extern "C" void kernel_launch(void* const* d_in, const int* in_sizes, int n_in,
                              void* d_out, int out_size)
{
    (void)in_sizes; (void)n_in; (void)out_size;
    const float* x     = (const float*)d_in[0];
    const float* w_qkv = (const float*)d_in[1];
    const float* b_qkv = (const float*)d_in[2];
    const float* w_o   = (const float*)d_in[3];
    const float* b_o   = (const float*)d_in[4];
    float* out = (float*)d_out;

    __nv_bfloat16 *xhi, *xlo, *wqt_h, *wqt_l, *wot_h, *wot_l;
    __nv_bfloat16 *qkvh, *qkvl, *ahi, *alo;
    cudaGetSymbolAddress((void**)&xhi,   g_xhi);
    cudaGetSymbolAddress((void**)&xlo,   g_xlo);
    cudaGetSymbolAddress((void**)&wqt_h, g_wqkvt_hi);
    cudaGetSymbolAddress((void**)&wqt_l, g_wqkvt_lo);
    cudaGetSymbolAddress((void**)&wot_h, g_wot_hi);
    cudaGetSymbolAddress((void**)&wot_l, g_wot_lo);
    cudaGetSymbolAddress((void**)&qkvh,  g_qkvh);
    cudaGetSymbolAddress((void**)&qkvl,  g_qkvl);
    cudaGetSymbolAddress((void**)&ahi,   g_ahi);
    cudaGetSymbolAddress((void**)&alo,   g_alo);

    // 1) Split x into bf16 hi/lo
    {
        int n4 = MROWS * DIM / 4;
        split_kernel<<<n4 / 256, 256>>>((const float4*)x, xhi, xlo, n4);
    }
    // 2) Transpose + split weights
    tsplit_kernel<<<dim3(N3 / 32, DIM / 32), dim3(32, 8)>>>(w_qkv, wqt_h, wqt_l, DIM, N3);
    tsplit_kernel<<<dim3(DIM / 32, DIM / 32), dim3(32, 8)>>>(w_o, wot_h, wot_l, DIM, DIM);

    // 3) QKV projection -> split bf16 output (feeds attention directly)
    gemm_hmma<1><<<dim3(N3 / 128, MROWS / 128), 512>>>(
        xhi, xlo, wqt_h, wqt_l, b_qkv, nullptr, qkvh, qkvl, MROWS, N3, DIM);

    // 4) Windowed causal attention (split-bf16 HMMA flash)
    attn_hmma<<<dim3(8, 512), 128>>>(qkvh, qkvl, ahi, alo);

    // 5) Output projection -> fp32 final output
    gemm_hmma<0><<<dim3(DIM / 128, MROWS / 128), 512>>>(
        ahi, alo, wot_h, wot_l, b_o, out, nullptr, nullptr, MROWS, DIM, DIM);
}

// round 5
// speedup vs baseline: 3.6279x; 1.5682x over previous
#include <cuda_runtime.h>
#include <cuda_fp16.h>
#include <math.h>
#include <stdint.h>

// Problem constants (fixed shapes)
#define BV      4
#define SEQ     4096
#define DIM     1024
#define WIN     512
#define HEADS   16
#define DH      64
#define MROWS   (BV * SEQ)     // 16384
#define N3      (3 * DIM)      // 3072
#define NEG_INF_F (-1e9f)

// ---------------------------------------------------------------------------
// Scratch (device globals: sanctioned workaround for the no-alloc rule)
// ---------------------------------------------------------------------------
__device__ __half g_xhi[(size_t)MROWS * DIM];
__device__ __half g_xlo[(size_t)MROWS * DIM];
__device__ __half g_wqkvt[(size_t)N3 * DIM];     // W_qkv^T [N3, K] fp16
__device__ __half g_wot[(size_t)DIM * DIM];      // W_o^T  [N, K] fp16
__device__ __half g_qkvh[(size_t)MROWS * N3];    // 96 MB
__device__ __half g_qkvl[(size_t)MROWS * N3];    // 96 MB
__device__ __half g_ahi[(size_t)MROWS * DIM];
__device__ __half g_alo[(size_t)MROWS * DIM];

// ---------------------------------------------------------------------------
// Helpers (sm_80-portable ISA: mma.sync + cp.async + ldmatrix)
// ---------------------------------------------------------------------------
__device__ __forceinline__ uint32_t smem_u32(const void* p) {
    uint32_t a;
    asm("{ .reg .u64 t; cvta.to.shared.u64 t, %1; cvt.u32.u64 %0, t; }"
        : "=r"(a) : "l"(p));
    return a;
}
#define CP16(dst, src) \
    asm volatile("cp.async.cg.shared.global [%0], [%1], 16;" \
                 :: "r"(dst), "l"(src) : "memory")
#define CP_COMMIT() asm volatile("cp.async.commit_group;" ::: "memory")
#define CP_WAIT1()  asm volatile("cp.async.wait_group 1;" ::: "memory")
#define CP_WAIT0()  asm volatile("cp.async.wait_group 0;" ::: "memory")

#define LDSM_X4(r0, r1, r2, r3, a) \
    asm volatile("ldmatrix.sync.aligned.m8n8.x4.shared.b16 {%0,%1,%2,%3}, [%4];" \
                 : "=r"(r0), "=r"(r1), "=r"(r2), "=r"(r3) : "r"(a))
#define LDSM_X4T(r0, r1, r2, r3, a) \
    asm volatile("ldmatrix.sync.aligned.m8n8.x4.trans.shared.b16 {%0,%1,%2,%3}, [%4];" \
                 : "=r"(r0), "=r"(r1), "=r"(r2), "=r"(r3) : "r"(a))

__device__ __forceinline__ void mma16816(float* d, const uint32_t* a, const uint32_t* b) {
    asm volatile(
        "mma.sync.aligned.m16n8k16.row.col.f32.f16.f16.f32 "
        "{%0,%1,%2,%3}, {%4,%5,%6,%7}, {%8,%9}, {%0,%1,%2,%3};"
        : "+f"(d[0]), "+f"(d[1]), "+f"(d[2]), "+f"(d[3])
        : "r"(a[0]), "r"(a[1]), "r"(a[2]), "r"(a[3]), "r"(b[0]), "r"(b[1]));
}

__device__ __forceinline__ uint32_t packh2(float a, float b) {
    __half2 t = __floats2half2_rn(a, b);
    return *reinterpret_cast<uint32_t*>(&t);
}

// ---------------------------------------------------------------------------
// 2-product fp16 HMMA GEMM: C[M,N] = (Ah+Al)[M,K] @ Bh^T + bias (B [N,K] fp16)
// Exactly A @ fp16(W): only error is fp16 weight rounding (~2^-12).
// CTA 128x128, 512 threads (16 warps, 32x32 warp tiles), BK=16/stage,
// 3-stage cp.async pipeline (3 bufs x 4KB per stage = 36KB), ldmatrix.
// SPLIT=0: fp32 C + bias.  SPLIT=1: fp16 hi/lo outputs + bias.
// Smem rows 32B (2 x 16B chunks), phys chunk = chunk ^ ((row>>2)&1).
// ---------------------------------------------------------------------------
template<int SPLIT>
__global__ __launch_bounds__(512, 2) void gemm_hmma(
    const __half* __restrict__ Ah, const __half* __restrict__ Al,
    const __half* __restrict__ Bh,
    const float* __restrict__ bias, float* __restrict__ C,
    __half* __restrict__ Ch, __half* __restrict__ Cl,
    int M, int N, int K)
{
    __shared__ char sm[36864];          // 3 stages x (3 bufs x 4KB)
    const uint32_t sb = smem_u32(sm);

    const int tid  = threadIdx.x;
    const int lane = tid & 31, wid = tid >> 5;
    const int g = lane >> 2, tig = lane & 3;
    const int jj = lane & 7, grp = lane >> 3;
    const int wm = (wid >> 2) * 32;
    const int wn = (wid & 3) * 32;
    const int row0 = blockIdx.y * 128, col0 = blockIdx.x * 128;

    // cp.async mapping: tid<256 -> Ah+Al chunks, tid>=256 -> Bh chunk
    const int lr = (tid & 255) >> 1;
    const int lc = tid & 1;
    const uint32_t swoff = lr * 32 + ((lc ^ ((lr >> 2) & 1)) << 4);
    const __half* gAh0 = Ah + (size_t)(row0 + lr) * K + lc * 8;
    const __half* gAl0 = Al + (size_t)(row0 + lr) * K + lc * 8;
    const __half* gB0  = Bh + (size_t)(col0 + lr) * K + lc * 8;

    // ldmatrix per-lane relative offsets (stage-invariant)
    uint32_t aoff[2], boff[2];
#pragma unroll
    for (int mt = 0; mt < 2; mt++) {
        int r = wm + mt * 16 + (grp & 1) * 8 + jj;
        int c = grp >> 1;
        aoff[mt] = r * 32 + ((c ^ ((r >> 2) & 1)) << 4);
    }
#pragma unroll
    for (int pr = 0; pr < 2; pr++) {
        int r = wn + pr * 16 + (grp >> 1) * 8 + jj;
        int c = grp & 1;
        boff[pr] = r * 32 + ((c ^ ((r >> 2) & 1)) << 4);
    }

    float acc[2][4][4];
#pragma unroll
    for (int mt = 0; mt < 2; mt++)
#pragma unroll
        for (int nt = 0; nt < 4; nt++)
#pragma unroll
            for (int j = 0; j < 4; j++) acc[mt][nt][j] = 0.f;

    const int nch = K >> 4;

    // Prologue: stages 0 and 1
#pragma unroll
    for (int s = 0; s < 2; s++) {
        const uint32_t so = s * 12288;
        const int ko = s * 16;
        if (tid < 256) {
            CP16(sb + so + swoff, gAh0 + ko);
            CP16(sb + so + 4096 + swoff, gAl0 + ko);
        } else {
            CP16(sb + so + 8192 + swoff, gB0 + ko);
        }
        CP_COMMIT();
    }

    for (int kc = 0; kc < nch; kc++) {
        if (kc + 1 < nch) { CP_WAIT1(); } else { CP_WAIT0(); }
        __syncthreads();
        if (kc + 2 < nch) {
            const uint32_t so = ((kc + 2) % 3) * 12288;
            const int ko = (kc + 2) * 16;
            if (tid < 256) {
                CP16(sb + so + swoff, gAh0 + ko);
                CP16(sb + so + 4096 + swoff, gAl0 + ko);
            } else {
                CP16(sb + so + 8192 + swoff, gB0 + ko);
            }
            CP_COMMIT();
        }

        const uint32_t st = sb + (kc % 3) * 12288;
        uint32_t ah[2][4], al[2][4], bh[4][2];
        LDSM_X4(ah[0][0], ah[0][1], ah[0][2], ah[0][3], st + aoff[0]);
        LDSM_X4(ah[1][0], ah[1][1], ah[1][2], ah[1][3], st + aoff[1]);
        LDSM_X4(al[0][0], al[0][1], al[0][2], al[0][3], st + 4096 + aoff[0]);
        LDSM_X4(al[1][0], al[1][1], al[1][2], al[1][3], st + 4096 + aoff[1]);
        LDSM_X4(bh[0][0], bh[0][1], bh[1][0], bh[1][1], st + 8192 + boff[0]);
        LDSM_X4(bh[2][0], bh[2][1], bh[3][0], bh[3][1], st + 8192 + boff[1]);

#pragma unroll
        for (int mt = 0; mt < 2; mt++)
#pragma unroll
            for (int nt = 0; nt < 4; nt++) {
                mma16816(acc[mt][nt], ah[mt], bh[nt]);
                mma16816(acc[mt][nt], al[mt], bh[nt]);
            }
    }

#pragma unroll
    for (int mt = 0; mt < 2; mt++) {
        const int r = row0 + wm + mt * 16 + g;
#pragma unroll
        for (int nt = 0; nt < 4; nt++) {
            const int c = col0 + wn + nt * 8 + tig * 2;
            const float bx = bias[c], by = bias[c + 1];
            float v00 = acc[mt][nt][0] + bx, v01 = acc[mt][nt][1] + by;
            float v10 = acc[mt][nt][2] + bx, v11 = acc[mt][nt][3] + by;
            if (SPLIT) {
                __half2 h0 = __floats2half2_rn(v00, v01);
                __half2 h1 = __floats2half2_rn(v10, v11);
                __half2 l0 = __floats2half2_rn(v00 - __low2float(h0),
                                               v01 - __high2float(h0));
                __half2 l1 = __floats2half2_rn(v10 - __low2float(h1),
                                               v11 - __high2float(h1));
                *(__half2*)&Ch[(size_t)r * N + c]       = h0;
                *(__half2*)&Ch[(size_t)(r + 8) * N + c] = h1;
                *(__half2*)&Cl[(size_t)r * N + c]       = l0;
                *(__half2*)&Cl[(size_t)(r + 8) * N + c] = l1;
            } else {
                float2 a0 = { v00, v01 }, a1 = { v10, v11 };
                *(float2*)&C[(size_t)r * N + c]       = a0;
                *(float2*)&C[(size_t)(r + 8) * N + c] = a1;
            }
        }
    }
}

// ---------------------------------------------------------------------------
// fp32 -> fp16 hi/lo split (elementwise)
// ---------------------------------------------------------------------------
__global__ __launch_bounds__(256) void split_kernel(
    const float4* __restrict__ in, __half* __restrict__ hi,
    __half* __restrict__ lo, int n4)
{
    int i = blockIdx.x * 256 + threadIdx.x;
    if (i >= n4) return;
    float4 v = in[i];
    __half2 h0 = __floats2half2_rn(v.x, v.y);
    __half2 h1 = __floats2half2_rn(v.z, v.w);
    __half2 l0 = __floats2half2_rn(v.x - __low2float(h0), v.y - __high2float(h0));
    __half2 l1 = __floats2half2_rn(v.z - __low2float(h1), v.w - __high2float(h1));
    ((__half2*)hi)[2 * i + 0] = h0;
    ((__half2*)hi)[2 * i + 1] = h1;
    ((__half2*)lo)[2 * i + 0] = l0;
    ((__half2*)lo)[2 * i + 1] = l1;
}

// ---------------------------------------------------------------------------
// Transpose: W [K, N] fp32 -> Wt [N, K] fp16 (hi only — weights)
// ---------------------------------------------------------------------------
__global__ __launch_bounds__(256) void tsplit_kernel(
    const float* __restrict__ W, __half* __restrict__ Th, int K, int N)
{
    __shared__ float t[32][33];
    const int nb = blockIdx.x * 32, kb = blockIdx.y * 32;
    const int tx = threadIdx.x, ty = threadIdx.y;
    for (int y = ty; y < 32; y += 8)
        t[y][tx] = W[(size_t)(kb + y) * N + nb + tx];
    __syncthreads();
    for (int y = ty; y < 32; y += 8)
        Th[(size_t)(nb + y) * K + kb + tx] = __float2half(t[tx][y]);
}

// ---------------------------------------------------------------------------
// Windowed causal attention, split-fp16 HMMA flash kernel (3-product).
// Block: 128 threads (4 warps). Grid: (8 q-tiles of 64 rows, 32 win x 16 heads).
// Smem (48KB): Qh 8K | Ql 8K | stage{0,1}: Kh 4K, Kl 4K, Vh 4K, Vl 4K.
// Tile rows are 128B (8 x 16B chunks); phys chunk = chunk ^ (row & 7).
// ---------------------------------------------------------------------------
__device__ __forceinline__ void attn_load_kv(
    uint32_t sstage, const __half* qh_g, const __half* ql_g,
    size_t rowbase, int tid)
{
#pragma unroll
    for (int it = 0; it < 8; it++) {
        int i = tid + it * 128;
        int buf = i >> 8, within = i & 255;
        int r = within >> 3, c = within & 7;
        uint32_t dst = sstage + buf * 4096 + r * 128 + ((c ^ (r & 7)) << 4);
        size_t go = rowbase + (size_t)r * N3 + c * 8;
        const __half* src;
        if (buf == 0)      src = qh_g + go + DIM;       // Kh
        else if (buf == 1) src = ql_g + go + DIM;       // Kl
        else if (buf == 2) src = qh_g + go + 2 * DIM;   // Vh
        else               src = ql_g + go + 2 * DIM;   // Vl
        CP16(dst, src);
    }
}

__global__ __launch_bounds__(128) void attn_hmma(
    const __half* __restrict__ qh_g, const __half* __restrict__ ql_g,
    __half* __restrict__ ohi, __half* __restrict__ olo)
{
    const int qt  = blockIdx.x;          // 0..7
    const int wh  = blockIdx.y;          // 0..511
    const int win = wh >> 4, h = wh & 15;
    const int mbase = win * WIN;
    const int qcol  = h * DH;
    const int tid = threadIdx.x, lane = tid & 31, w = tid >> 5;
    const int g = lane >> 2, tig = lane & 3;
    const int jj = lane & 7, grp = lane >> 3;

    __shared__ char sm[49152];
    const uint32_t sb = smem_u32(sm);

    // Load Q tile [64 x 64] hi/lo (vectorized stores, swizzled)
    for (int i = tid; i < 512; i += 128) {
        int r = i >> 3, c = i & 7;
        uint32_t off = r * 128 + ((c ^ (r & 7)) << 4);
        size_t gsrc = (size_t)(mbase + qt * 64 + r) * N3 + qcol + c * 8;
        *(uint4*)(sm + off)        = *(const uint4*)(qh_g + gsrc);
        *(uint4*)(sm + 8192 + off) = *(const uint4*)(ql_g + gsrc);
    }

    const int ktmax = 2 * qt + 1;
    attn_load_kv(sb + 16384, qh_g, ql_g, (size_t)mbase * N3 + qcol, tid);
    CP_COMMIT();
    __syncthreads();

    // Q fragments (registers, whole block)
    uint32_t qfh[4][4], qfl[4][4];
    const int qrow = w * 16 + (grp & 1) * 8 + jj;
#pragma unroll
    for (int kk = 0; kk < 4; kk++) {
        int c = 2 * kk + (grp >> 1);
        uint32_t off = qrow * 128 + ((c ^ (qrow & 7)) << 4);
        LDSM_X4(qfh[kk][0], qfh[kk][1], qfh[kk][2], qfh[kk][3], sb + off);
        LDSM_X4(qfl[kk][0], qfl[kk][1], qfl[kk][2], qfl[kk][3], sb + 8192 + off);
    }

    float m0 = -INFINITY, m1 = -INFINITY, l0 = 0.f, l1 = 0.f;
    float oacc[8][4];
#pragma unroll
    for (int nt = 0; nt < 8; nt++)
#pragma unroll
        for (int j = 0; j < 4; j++) oacc[nt][j] = 0.f;

    const int gq0 = qt * 64 + w * 16 + g;
    const int gq1 = gq0 + 8;
    const int krowb = (grp >> 1) * 8 + jj;
    const int vrow0 = (grp & 1) * 8 + jj;

    for (int kt = 0; kt <= ktmax; kt++) {
        CP_WAIT0();
        __syncthreads();
        if (kt < ktmax) {
            attn_load_kv(sb + 16384 + ((kt + 1) & 1) * 16384, qh_g, ql_g,
                         (size_t)(mbase + (kt + 1) * 32) * N3 + qcol, tid);
            CP_COMMIT();
        }

        const uint32_t stg = sb + 16384 + (kt & 1) * 16384;

        // ---- S = Q K^T (split, 3 products) ----
        float sacc[4][4];
#pragma unroll
        for (int nt = 0; nt < 4; nt++)
#pragma unroll
            for (int j = 0; j < 4; j++) sacc[nt][j] = 0.f;

#pragma unroll
        for (int kk = 0; kk < 4; kk++) {
            uint32_t kbh[4][2], kbl[4][2];
#pragma unroll
            for (int pr = 0; pr < 2; pr++) {
                int r = pr * 16 + krowb;
                int c = 2 * kk + (grp & 1);
                uint32_t off = r * 128 + ((c ^ (r & 7)) << 4);
                LDSM_X4(kbh[pr*2][0], kbh[pr*2][1], kbh[pr*2+1][0], kbh[pr*2+1][1],
                        stg + off);
                LDSM_X4(kbl[pr*2][0], kbl[pr*2][1], kbl[pr*2+1][0], kbl[pr*2+1][1],
                        stg + 4096 + off);
            }
#pragma unroll
            for (int nt = 0; nt < 4; nt++) {
                mma16816(sacc[nt], qfh[kk], kbh[nt]);
                mma16816(sacc[nt], qfh[kk], kbl[nt]);
                mma16816(sacc[nt], qfl[kk], kbh[nt]);
            }
        }

        // ---- scale + causal mask ----
#pragma unroll
        for (int nt = 0; nt < 4; nt++) {
            int colb = kt * 32 + nt * 8 + 2 * tig;
            sacc[nt][0] = (colb     > gq0) ? NEG_INF_F : sacc[nt][0] * 0.125f;
            sacc[nt][1] = (colb + 1 > gq0) ? NEG_INF_F : sacc[nt][1] * 0.125f;
            sacc[nt][2] = (colb     > gq1) ? NEG_INF_F : sacc[nt][2] * 0.125f;
            sacc[nt][3] = (colb + 1 > gq1) ? NEG_INF_F : sacc[nt][3] * 0.125f;
        }

        // ---- online softmax (rows g, g+8; reduce over tig lanes) ----
        float rm0 = fmaxf(fmaxf(sacc[0][0], sacc[0][1]), fmaxf(sacc[1][0], sacc[1][1]));
        rm0 = fmaxf(rm0, fmaxf(fmaxf(sacc[2][0], sacc[2][1]), fmaxf(sacc[3][0], sacc[3][1])));
        float rm1 = fmaxf(fmaxf(sacc[0][2], sacc[0][3]), fmaxf(sacc[1][2], sacc[1][3]));
        rm1 = fmaxf(rm1, fmaxf(fmaxf(sacc[2][2], sacc[2][3]), fmaxf(sacc[3][2], sacc[3][3])));
        rm0 = fmaxf(rm0, __shfl_xor_sync(0xffffffffu, rm0, 1));
        rm0 = fmaxf(rm0, __shfl_xor_sync(0xffffffffu, rm0, 2));
        rm1 = fmaxf(rm1, __shfl_xor_sync(0xffffffffu, rm1, 1));
        rm1 = fmaxf(rm1, __shfl_xor_sync(0xffffffffu, rm1, 2));

        float mn0 = fmaxf(m0, rm0), mn1 = fmaxf(m1, rm1);
        float corr0 = __expf(m0 - mn0), corr1 = __expf(m1 - mn1);
        m0 = mn0; m1 = mn1;

        float rs0 = 0.f, rs1 = 0.f;
#pragma unroll
        for (int nt = 0; nt < 4; nt++) {
            sacc[nt][0] = __expf(sacc[nt][0] - mn0);
            sacc[nt][1] = __expf(sacc[nt][1] - mn0);
            sacc[nt][2] = __expf(sacc[nt][2] - mn1);
            sacc[nt][3] = __expf(sacc[nt][3] - mn1);
            rs0 += sacc[nt][0] + sacc[nt][1];
            rs1 += sacc[nt][2] + sacc[nt][3];
        }
        rs0 += __shfl_xor_sync(0xffffffffu, rs0, 1);
        rs0 += __shfl_xor_sync(0xffffffffu, rs0, 2);
        rs1 += __shfl_xor_sync(0xffffffffu, rs1, 1);
        rs1 += __shfl_xor_sync(0xffffffffu, rs1, 2);
        l0 = l0 * corr0 + rs0;
        l1 = l1 * corr1 + rs1;

#pragma unroll
        for (int nt = 0; nt < 8; nt++) {
            oacc[nt][0] *= corr0; oacc[nt][1] *= corr0;
            oacc[nt][2] *= corr1; oacc[nt][3] *= corr1;
        }

        // ---- P fragments (FA2 identity: C-frag == A-frag layout) ----
        uint32_t pah[2][4], pal[2][4];
#pragma unroll
        for (int kk2 = 0; kk2 < 2; kk2++) {
            int a = 2 * kk2, b = a + 1;
            pah[kk2][0] = packh2(sacc[a][0], sacc[a][1]);
            pah[kk2][1] = packh2(sacc[a][2], sacc[a][3]);
            pah[kk2][2] = packh2(sacc[b][0], sacc[b][1]);
            pah[kk2][3] = packh2(sacc[b][2], sacc[b][3]);
            __half2* t;
            t = (__half2*)&pah[kk2][0];
            pal[kk2][0] = packh2(sacc[a][0] - __low2float(*t),
                                 sacc[a][1] - __high2float(*t));
            t = (__half2*)&pah[kk2][1];
            pal[kk2][1] = packh2(sacc[a][2] - __low2float(*t),
                                 sacc[a][3] - __high2float(*t));
            t = (__half2*)&pah[kk2][2];
            pal[kk2][2] = packh2(sacc[b][0] - __low2float(*t),
                                 sacc[b][1] - __high2float(*t));
            t = (__half2*)&pah[kk2][3];
            pal[kk2][3] = packh2(sacc[b][2] - __low2float(*t),
                                 sacc[b][3] - __high2float(*t));
        }

        // ---- O += P V (split, 3 products); V via ldmatrix.trans ----
#pragma unroll
        for (int kk2 = 0; kk2 < 2; kk2++) {
            int r = kk2 * 16 + vrow0;
#pragma unroll
            for (int pr = 0; pr < 4; pr++) {
                int c = pr * 2 + (grp >> 1);
                uint32_t off = r * 128 + ((c ^ (r & 7)) << 4);
                uint32_t vh0[2], vh1[2], vl0[2], vl1[2];
                LDSM_X4T(vh0[0], vh0[1], vh1[0], vh1[1], stg + 8192 + off);
                LDSM_X4T(vl0[0], vl0[1], vl1[0], vl1[1], stg + 12288 + off);
                mma16816(oacc[pr*2],   pah[kk2], vh0);
                mma16816(oacc[pr*2],   pal[kk2], vh0);
                mma16816(oacc[pr*2],   pah[kk2], vl0);
                mma16816(oacc[pr*2+1], pah[kk2], vh1);
                mma16816(oacc[pr*2+1], pal[kk2], vh1);
                mma16816(oacc[pr*2+1], pah[kk2], vl1);
            }
        }
    }

    // ---- epilogue: normalize + split-fp16 store ----
    const float inv0 = 1.f / l0, inv1 = 1.f / l1;
    const size_t r0 = (size_t)(mbase + qt * 64 + w * 16 + g);
    const size_t r1 = r0 + 8;
#pragma unroll
    for (int nt = 0; nt < 8; nt++) {
        int c = qcol + nt * 8 + tig * 2;
        float v00 = oacc[nt][0] * inv0, v01 = oacc[nt][1] * inv0;
        float v10 = oacc[nt][2] * inv1, v11 = oacc[nt][3] * inv1;
        __half2 h0 = __floats2half2_rn(v00, v01);
        __half2 h1 = __floats2half2_rn(v10, v11);
        *(__half2*)&ohi[r0 * DIM + c] = h0;
        *(__half2*)&ohi[r1 * DIM + c] = h1;
        *(__half2*)&olo[r0 * DIM + c] =
            __floats2half2_rn(v00 - __low2float(h0), v01 - __high2float(h0));
        *(__half2*)&olo[r1 * DIM + c] =
            __floats2half2_rn(v10 - __low2float(h1), v11 - __high2float(h1));
    }
}

// ---------------------------------------------------------------------------
extern "C" void kernel_launch(void* const* d_in, const int* in_sizes, int n_in,
                              void* d_out, int out_size)
{
    (void)in_sizes; (void)n_in; (void)out_size;
    const float* x     = (const float*)d_in[0];
    const float* w_qkv = (const float*)d_in[1];
    const float* b_qkv = (const float*)d_in[2];
    const float* w_o   = (const float*)d_in[3];
    const float* b_o   = (const float*)d_in[4];
    float* out = (float*)d_out;

    __half *xhi, *xlo, *wqt, *wot, *qkvh, *qkvl, *ahi, *alo;
    cudaGetSymbolAddress((void**)&xhi,  g_xhi);
    cudaGetSymbolAddress((void**)&xlo,  g_xlo);
    cudaGetSymbolAddress((void**)&wqt,  g_wqkvt);
    cudaGetSymbolAddress((void**)&wot,  g_wot);
    cudaGetSymbolAddress((void**)&qkvh, g_qkvh);
    cudaGetSymbolAddress((void**)&qkvl, g_qkvl);
    cudaGetSymbolAddress((void**)&ahi,  g_ahi);
    cudaGetSymbolAddress((void**)&alo,  g_alo);

    // 1) Split x into fp16 hi/lo
    {
        int n4 = MROWS * DIM / 4;
        split_kernel<<<n4 / 256, 256>>>((const float4*)x, xhi, xlo, n4);
    }
    // 2) Transpose weights to fp16
    tsplit_kernel<<<dim3(N3 / 32, DIM / 32), dim3(32, 8)>>>(w_qkv, wqt, DIM, N3);
    tsplit_kernel<<<dim3(DIM / 32, DIM / 32), dim3(32, 8)>>>(w_o, wot, DIM, DIM);

    // 3) QKV projection -> split fp16 output (feeds attention directly)
    gemm_hmma<1><<<dim3(N3 / 128, MROWS / 128), 512>>>(
        xhi, xlo, wqt, b_qkv, nullptr, qkvh, qkvl, MROWS, N3, DIM);

    // 4) Windowed causal attention (split-fp16 HMMA flash)
    attn_hmma<<<dim3(8, 512), 128>>>(qkvh, qkvl, ahi, alo);

    // 5) Output projection -> fp32 final output
    gemm_hmma<0><<<dim3(DIM / 128, MROWS / 128), 512>>>(
        ahi, alo, wot, b_o, out, nullptr, nullptr, MROWS, DIM, DIM);
}

// round 6
// speedup vs baseline: 4.3780x; 1.2068x over previous
#include <cuda_runtime.h>
#include <cuda_fp16.h>
#include <math.h>
#include <stdint.h>

// Problem constants (fixed shapes)
#define BV      4
#define SEQ     4096
#define DIM     1024
#define WIN     512
#define HEADS   16
#define DH      64
#define MROWS   (BV * SEQ)     // 16384
#define N3      (3 * DIM)      // 3072
#define NEG_INF_F (-1e9f)

// ---------------------------------------------------------------------------
// Scratch (device globals: sanctioned workaround for the no-alloc rule)
// ---------------------------------------------------------------------------
__device__ __half g_xhi[(size_t)MROWS * DIM];
__device__ __half g_xlo[(size_t)MROWS * DIM];
__device__ __half g_wqkvt[(size_t)N3 * DIM];     // W_qkv^T [N3, K] fp16
__device__ __half g_wot[(size_t)DIM * DIM];      // W_o^T  [N, K] fp16
__device__ __half g_qkvh[(size_t)MROWS * N3];    // 96 MB
__device__ __half g_qkvl[(size_t)MROWS * N3];    // 96 MB
__device__ __half g_ahi[(size_t)MROWS * DIM];
__device__ __half g_alo[(size_t)MROWS * DIM];

// ---------------------------------------------------------------------------
// Helpers (sm_80-portable ISA: mma.sync + cp.async + ldmatrix)
// ---------------------------------------------------------------------------
__device__ __forceinline__ uint32_t smem_u32(const void* p) {
    uint32_t a;
    asm("{ .reg .u64 t; cvta.to.shared.u64 t, %1; cvt.u32.u64 %0, t; }"
        : "=r"(a) : "l"(p));
    return a;
}
#define CP16(dst, src) \
    asm volatile("cp.async.cg.shared.global [%0], [%1], 16;" \
                 :: "r"(dst), "l"(src) : "memory")
#define CP_COMMIT() asm volatile("cp.async.commit_group;" ::: "memory")
#define CP_WAIT1()  asm volatile("cp.async.wait_group 1;" ::: "memory")
#define CP_WAIT0()  asm volatile("cp.async.wait_group 0;" ::: "memory")

#define LDSM_X4(r0, r1, r2, r3, a) \
    asm volatile("ldmatrix.sync.aligned.m8n8.x4.shared.b16 {%0,%1,%2,%3}, [%4];" \
                 : "=r"(r0), "=r"(r1), "=r"(r2), "=r"(r3) : "r"(a))
#define LDSM_X4T(r0, r1, r2, r3, a) \
    asm volatile("ldmatrix.sync.aligned.m8n8.x4.trans.shared.b16 {%0,%1,%2,%3}, [%4];" \
                 : "=r"(r0), "=r"(r1), "=r"(r2), "=r"(r3) : "r"(a))

__device__ __forceinline__ void mma16816(float* d, const uint32_t* a, const uint32_t* b) {
    asm volatile(
        "mma.sync.aligned.m16n8k16.row.col.f32.f16.f16.f32 "
        "{%0,%1,%2,%3}, {%4,%5,%6,%7}, {%8,%9}, {%0,%1,%2,%3};"
        : "+f"(d[0]), "+f"(d[1]), "+f"(d[2]), "+f"(d[3])
        : "r"(a[0]), "r"(a[1]), "r"(a[2]), "r"(a[3]), "r"(b[0]), "r"(b[1]));
}

__device__ __forceinline__ uint32_t packh2(float a, float b) {
    __half2 t = __floats2half2_rn(a, b);
    return *reinterpret_cast<uint32_t*>(&t);
}

// ---------------------------------------------------------------------------
// 2-product fp16 HMMA GEMM: C[M,N] = (Ah+Al)[M,K] @ Bh^T + bias (B [N,K] fp16)
// Exactly A @ fp16(W): only error is fp16 weight rounding (~2^-12).
// CTA 128x128, 256 threads (8 warps, 32x64 warp tiles -> 4:1 MMA:LDSM),
// BK=16/stage, 3-stage cp.async pipeline (36KB), ldmatrix fragment loads.
// SPLIT=0: fp32 C + bias.  SPLIT=1: fp16 hi/lo outputs + bias.
// Smem rows 32B (2 x 16B chunks), phys chunk = chunk ^ ((row>>2)&1).
// ---------------------------------------------------------------------------
template<int SPLIT>
__global__ __launch_bounds__(256, 2) void gemm_hmma(
    const __half* __restrict__ Ah, const __half* __restrict__ Al,
    const __half* __restrict__ Bh,
    const float* __restrict__ bias, float* __restrict__ C,
    __half* __restrict__ Ch, __half* __restrict__ Cl,
    int M, int N, int K)
{
    __shared__ char sm[36864];          // 3 stages x (3 bufs x 4KB)
    const uint32_t sb = smem_u32(sm);

    const int tid  = threadIdx.x;
    const int lane = tid & 31, wid = tid >> 5;
    const int g = lane >> 2, tig = lane & 3;
    const int jj = lane & 7, grp = lane >> 3;
    const int wm = (wid & 3) * 32;      // 4 warps down M
    const int wn = (wid >> 2) * 64;     // 2 warps across N
    const int row0 = blockIdx.y * 128, col0 = blockIdx.x * 128;

    // cp.async mapping: each thread loads one 16B chunk in each of 3 bufs
    const int lr = tid >> 1;            // row 0..127
    const int lc = tid & 1;             // 16B chunk 0/1
    const uint32_t swoff = lr * 32 + ((lc ^ ((lr >> 2) & 1)) << 4);
    const __half* gAh0 = Ah + (size_t)(row0 + lr) * K + lc * 8;
    const __half* gAl0 = Al + (size_t)(row0 + lr) * K + lc * 8;
    const __half* gB0  = Bh + (size_t)(col0 + lr) * K + lc * 8;

    // ldmatrix per-lane relative offsets (stage-invariant)
    uint32_t aoff[2], boff[4];
#pragma unroll
    for (int mt = 0; mt < 2; mt++) {
        int r = wm + mt * 16 + (grp & 1) * 8 + jj;
        int c = grp >> 1;
        aoff[mt] = r * 32 + ((c ^ ((r >> 2) & 1)) << 4);
    }
#pragma unroll
    for (int bt = 0; bt < 4; bt++) {
        int r = wn + bt * 16 + (grp >> 1) * 8 + jj;
        int c = grp & 1;
        boff[bt] = r * 32 + ((c ^ ((r >> 2) & 1)) << 4);
    }

    float acc[2][8][4];
#pragma unroll
    for (int mt = 0; mt < 2; mt++)
#pragma unroll
        for (int nf = 0; nf < 8; nf++)
#pragma unroll
            for (int j = 0; j < 4; j++) acc[mt][nf][j] = 0.f;

    const int nch = K >> 4;

    // Prologue: stages 0 and 1
#pragma unroll
    for (int s = 0; s < 2; s++) {
        const uint32_t so = s * 12288;
        const int ko = s * 16;
        CP16(sb + so + swoff, gAh0 + ko);
        CP16(sb + so + 4096 + swoff, gAl0 + ko);
        CP16(sb + so + 8192 + swoff, gB0 + ko);
        CP_COMMIT();
    }

    for (int kc = 0; kc < nch; kc++) {
        if (kc + 1 < nch) { CP_WAIT1(); } else { CP_WAIT0(); }
        __syncthreads();
        if (kc + 2 < nch) {
            const uint32_t so = ((kc + 2) % 3) * 12288;
            const int ko = (kc + 2) * 16;
            CP16(sb + so + swoff, gAh0 + ko);
            CP16(sb + so + 4096 + swoff, gAl0 + ko);
            CP16(sb + so + 8192 + swoff, gB0 + ko);
            CP_COMMIT();
        }

        const uint32_t st = sb + (kc % 3) * 12288;
        uint32_t ah[2][4], al[2][4], bh[8][2];
        LDSM_X4(ah[0][0], ah[0][1], ah[0][2], ah[0][3], st + aoff[0]);
        LDSM_X4(ah[1][0], ah[1][1], ah[1][2], ah[1][3], st + aoff[1]);
        LDSM_X4(al[0][0], al[0][1], al[0][2], al[0][3], st + 4096 + aoff[0]);
        LDSM_X4(al[1][0], al[1][1], al[1][2], al[1][3], st + 4096 + aoff[1]);
#pragma unroll
        for (int bt = 0; bt < 4; bt++)
            LDSM_X4(bh[2*bt][0], bh[2*bt][1], bh[2*bt+1][0], bh[2*bt+1][1],
                    st + 8192 + boff[bt]);

#pragma unroll
        for (int mt = 0; mt < 2; mt++)
#pragma unroll
            for (int nf = 0; nf < 8; nf++) {
                mma16816(acc[mt][nf], ah[mt], bh[nf]);
                mma16816(acc[mt][nf], al[mt], bh[nf]);
            }
    }

#pragma unroll
    for (int mt = 0; mt < 2; mt++) {
        const int r = row0 + wm + mt * 16 + g;
#pragma unroll
        for (int nf = 0; nf < 8; nf++) {
            const int c = col0 + wn + nf * 8 + tig * 2;
            const float bx = bias[c], by = bias[c + 1];
            float v00 = acc[mt][nf][0] + bx, v01 = acc[mt][nf][1] + by;
            float v10 = acc[mt][nf][2] + bx, v11 = acc[mt][nf][3] + by;
            if (SPLIT) {
                __half2 h0 = __floats2half2_rn(v00, v01);
                __half2 h1 = __floats2half2_rn(v10, v11);
                __half2 l0 = __floats2half2_rn(v00 - __low2float(h0),
                                               v01 - __high2float(h0));
                __half2 l1 = __floats2half2_rn(v10 - __low2float(h1),
                                               v11 - __high2float(h1));
                *(__half2*)&Ch[(size_t)r * N + c]       = h0;
                *(__half2*)&Ch[(size_t)(r + 8) * N + c] = h1;
                *(__half2*)&Cl[(size_t)r * N + c]       = l0;
                *(__half2*)&Cl[(size_t)(r + 8) * N + c] = l1;
            } else {
                float2 a0 = { v00, v01 }, a1 = { v10, v11 };
                *(float2*)&C[(size_t)r * N + c]       = a0;
                *(float2*)&C[(size_t)(r + 8) * N + c] = a1;
            }
        }
    }
}

// ---------------------------------------------------------------------------
// fp32 -> fp16 hi/lo split (elementwise)
// ---------------------------------------------------------------------------
__global__ __launch_bounds__(256) void split_kernel(
    const float4* __restrict__ in, __half* __restrict__ hi,
    __half* __restrict__ lo, int n4)
{
    int i = blockIdx.x * 256 + threadIdx.x;
    if (i >= n4) return;
    float4 v = in[i];
    __half2 h0 = __floats2half2_rn(v.x, v.y);
    __half2 h1 = __floats2half2_rn(v.z, v.w);
    __half2 l0 = __floats2half2_rn(v.x - __low2float(h0), v.y - __high2float(h0));
    __half2 l1 = __floats2half2_rn(v.z - __low2float(h1), v.w - __high2float(h1));
    ((__half2*)hi)[2 * i + 0] = h0;
    ((__half2*)hi)[2 * i + 1] = h1;
    ((__half2*)lo)[2 * i + 0] = l0;
    ((__half2*)lo)[2 * i + 1] = l1;
}

// ---------------------------------------------------------------------------
// Transpose: W [K, N] fp32 -> Wt [N, K] fp16 (weights)
// ---------------------------------------------------------------------------
__global__ __launch_bounds__(256) void tsplit_kernel(
    const float* __restrict__ W, __half* __restrict__ Th, int K, int N)
{
    __shared__ float t[32][33];
    const int nb = blockIdx.x * 32, kb = blockIdx.y * 32;
    const int tx = threadIdx.x, ty = threadIdx.y;
    for (int y = ty; y < 32; y += 8)
        t[y][tx] = W[(size_t)(kb + y) * N + nb + tx];
    __syncthreads();
    for (int y = ty; y < 32; y += 8)
        Th[(size_t)(nb + y) * K + kb + tx] = __float2half(t[tx][y]);
}

// ---------------------------------------------------------------------------
// Windowed causal attention, split-fp16 HMMA flash kernel (3-product).
// Block: 128 threads (4 warps). Grid: (8 q-tiles of 64 rows, 32 win x 16 heads).
// Smem (48KB): Qh 8K | Ql 8K | stage{0,1}: Kh 4K, Kl 4K, Vh 4K, Vl 4K.
// Tile rows are 128B (8 x 16B chunks); phys chunk = chunk ^ (row & 7).
// ---------------------------------------------------------------------------
__device__ __forceinline__ void attn_load_kv(
    uint32_t sstage, const __half* qh_g, const __half* ql_g,
    size_t rowbase, int tid)
{
#pragma unroll
    for (int it = 0; it < 8; it++) {
        int i = tid + it * 128;
        int buf = i >> 8, within = i & 255;
        int r = within >> 3, c = within & 7;
        uint32_t dst = sstage + buf * 4096 + r * 128 + ((c ^ (r & 7)) << 4);
        size_t go = rowbase + (size_t)r * N3 + c * 8;
        const __half* src;
        if (buf == 0)      src = qh_g + go + DIM;       // Kh
        else if (buf == 1) src = ql_g + go + DIM;       // Kl
        else if (buf == 2) src = qh_g + go + 2 * DIM;   // Vh
        else               src = ql_g + go + 2 * DIM;   // Vl
        CP16(dst, src);
    }
}

__global__ __launch_bounds__(128) void attn_hmma(
    const __half* __restrict__ qh_g, const __half* __restrict__ ql_g,
    __half* __restrict__ ohi, __half* __restrict__ olo)
{
    const int qt  = blockIdx.x;          // 0..7
    const int wh  = blockIdx.y;          // 0..511
    const int win = wh >> 4, h = wh & 15;
    const int mbase = win * WIN;
    const int qcol  = h * DH;
    const int tid = threadIdx.x, lane = tid & 31, w = tid >> 5;
    const int g = lane >> 2, tig = lane & 3;
    const int jj = lane & 7, grp = lane >> 3;

    __shared__ char sm[49152];
    const uint32_t sb = smem_u32(sm);

    // Load Q tile [64 x 64] hi/lo (vectorized stores, swizzled)
    for (int i = tid; i < 512; i += 128) {
        int r = i >> 3, c = i & 7;
        uint32_t off = r * 128 + ((c ^ (r & 7)) << 4);
        size_t gsrc = (size_t)(mbase + qt * 64 + r) * N3 + qcol + c * 8;
        *(uint4*)(sm + off)        = *(const uint4*)(qh_g + gsrc);
        *(uint4*)(sm + 8192 + off) = *(const uint4*)(ql_g + gsrc);
    }

    const int ktmax = 2 * qt + 1;
    attn_load_kv(sb + 16384, qh_g, ql_g, (size_t)mbase * N3 + qcol, tid);
    CP_COMMIT();
    __syncthreads();

    // Q fragments (registers, whole block)
    uint32_t qfh[4][4], qfl[4][4];
    const int qrow = w * 16 + (grp & 1) * 8 + jj;
#pragma unroll
    for (int kk = 0; kk < 4; kk++) {
        int c = 2 * kk + (grp >> 1);
        uint32_t off = qrow * 128 + ((c ^ (qrow & 7)) << 4);
        LDSM_X4(qfh[kk][0], qfh[kk][1], qfh[kk][2], qfh[kk][3], sb + off);
        LDSM_X4(qfl[kk][0], qfl[kk][1], qfl[kk][2], qfl[kk][3], sb + 8192 + off);
    }

    float m0 = -INFINITY, m1 = -INFINITY, l0 = 0.f, l1 = 0.f;
    float oacc[8][4];
#pragma unroll
    for (int nt = 0; nt < 8; nt++)
#pragma unroll
        for (int j = 0; j < 4; j++) oacc[nt][j] = 0.f;

    const int gq0 = qt * 64 + w * 16 + g;
    const int gq1 = gq0 + 8;
    const int krowb = (grp >> 1) * 8 + jj;
    const int vrow0 = (grp & 1) * 8 + jj;

    for (int kt = 0; kt <= ktmax; kt++) {
        CP_WAIT0();
        __syncthreads();
        if (kt < ktmax) {
            attn_load_kv(sb + 16384 + ((kt + 1) & 1) * 16384, qh_g, ql_g,
                         (size_t)(mbase + (kt + 1) * 32) * N3 + qcol, tid);
            CP_COMMIT();
        }

        const uint32_t stg = sb + 16384 + (kt & 1) * 16384;

        // ---- S = Q K^T (split, 3 products) ----
        float sacc[4][4];
#pragma unroll
        for (int nt = 0; nt < 4; nt++)
#pragma unroll
            for (int j = 0; j < 4; j++) sacc[nt][j] = 0.f;

#pragma unroll
        for (int kk = 0; kk < 4; kk++) {
            uint32_t kbh[4][2], kbl[4][2];
#pragma unroll
            for (int pr = 0; pr < 2; pr++) {
                int r = pr * 16 + krowb;
                int c = 2 * kk + (grp & 1);
                uint32_t off = r * 128 + ((c ^ (r & 7)) << 4);
                LDSM_X4(kbh[pr*2][0], kbh[pr*2][1], kbh[pr*2+1][0], kbh[pr*2+1][1],
                        stg + off);
                LDSM_X4(kbl[pr*2][0], kbl[pr*2][1], kbl[pr*2+1][0], kbl[pr*2+1][1],
                        stg + 4096 + off);
            }
#pragma unroll
            for (int nt = 0; nt < 4; nt++) {
                mma16816(sacc[nt], qfh[kk], kbh[nt]);
                mma16816(sacc[nt], qfh[kk], kbl[nt]);
                mma16816(sacc[nt], qfl[kk], kbh[nt]);
            }
        }

        // ---- scale + causal mask ----
#pragma unroll
        for (int nt = 0; nt < 4; nt++) {
            int colb = kt * 32 + nt * 8 + 2 * tig;
            sacc[nt][0] = (colb     > gq0) ? NEG_INF_F : sacc[nt][0] * 0.125f;
            sacc[nt][1] = (colb + 1 > gq0) ? NEG_INF_F : sacc[nt][1] * 0.125f;
            sacc[nt][2] = (colb     > gq1) ? NEG_INF_F : sacc[nt][2] * 0.125f;
            sacc[nt][3] = (colb + 1 > gq1) ? NEG_INF_F : sacc[nt][3] * 0.125f;
        }

        // ---- online softmax (rows g, g+8; reduce over tig lanes) ----
        float rm0 = fmaxf(fmaxf(sacc[0][0], sacc[0][1]), fmaxf(sacc[1][0], sacc[1][1]));
        rm0 = fmaxf(rm0, fmaxf(fmaxf(sacc[2][0], sacc[2][1]), fmaxf(sacc[3][0], sacc[3][1])));
        float rm1 = fmaxf(fmaxf(sacc[0][2], sacc[0][3]), fmaxf(sacc[1][2], sacc[1][3]));
        rm1 = fmaxf(rm1, fmaxf(fmaxf(sacc[2][2], sacc[2][3]), fmaxf(sacc[3][2], sacc[3][3])));
        rm0 = fmaxf(rm0, __shfl_xor_sync(0xffffffffu, rm0, 1));
        rm0 = fmaxf(rm0, __shfl_xor_sync(0xffffffffu, rm0, 2));
        rm1 = fmaxf(rm1, __shfl_xor_sync(0xffffffffu, rm1, 1));
        rm1 = fmaxf(rm1, __shfl_xor_sync(0xffffffffu, rm1, 2));

        float mn0 = fmaxf(m0, rm0), mn1 = fmaxf(m1, rm1);
        float corr0 = __expf(m0 - mn0), corr1 = __expf(m1 - mn1);
        m0 = mn0; m1 = mn1;

        float rs0 = 0.f, rs1 = 0.f;
#pragma unroll
        for (int nt = 0; nt < 4; nt++) {
            sacc[nt][0] = __expf(sacc[nt][0] - mn0);
            sacc[nt][1] = __expf(sacc[nt][1] - mn0);
            sacc[nt][2] = __expf(sacc[nt][2] - mn1);
            sacc[nt][3] = __expf(sacc[nt][3] - mn1);
            rs0 += sacc[nt][0] + sacc[nt][1];
            rs1 += sacc[nt][2] + sacc[nt][3];
        }
        rs0 += __shfl_xor_sync(0xffffffffu, rs0, 1);
        rs0 += __shfl_xor_sync(0xffffffffu, rs0, 2);
        rs1 += __shfl_xor_sync(0xffffffffu, rs1, 1);
        rs1 += __shfl_xor_sync(0xffffffffu, rs1, 2);
        l0 = l0 * corr0 + rs0;
        l1 = l1 * corr1 + rs1;

#pragma unroll
        for (int nt = 0; nt < 8; nt++) {
            oacc[nt][0] *= corr0; oacc[nt][1] *= corr0;
            oacc[nt][2] *= corr1; oacc[nt][3] *= corr1;
        }

        // ---- P fragments (FA2 identity: C-frag == A-frag layout) ----
        uint32_t pah[2][4], pal[2][4];
#pragma unroll
        for (int kk2 = 0; kk2 < 2; kk2++) {
            int a = 2 * kk2, b = a + 1;
            pah[kk2][0] = packh2(sacc[a][0], sacc[a][1]);
            pah[kk2][1] = packh2(sacc[a][2], sacc[a][3]);
            pah[kk2][2] = packh2(sacc[b][0], sacc[b][1]);
            pah[kk2][3] = packh2(sacc[b][2], sacc[b][3]);
            __half2* t;
            t = (__half2*)&pah[kk2][0];
            pal[kk2][0] = packh2(sacc[a][0] - __low2float(*t),
                                 sacc[a][1] - __high2float(*t));
            t = (__half2*)&pah[kk2][1];
            pal[kk2][1] = packh2(sacc[a][2] - __low2float(*t),
                                 sacc[a][3] - __high2float(*t));
            t = (__half2*)&pah[kk2][2];
            pal[kk2][2] = packh2(sacc[b][0] - __low2float(*t),
                                 sacc[b][1] - __high2float(*t));
            t = (__half2*)&pah[kk2][3];
            pal[kk2][3] = packh2(sacc[b][2] - __low2float(*t),
                                 sacc[b][3] - __high2float(*t));
        }

        // ---- O += P V (split, 3 products); V via ldmatrix.trans ----
#pragma unroll
        for (int kk2 = 0; kk2 < 2; kk2++) {
            int r = kk2 * 16 + vrow0;
#pragma unroll
            for (int pr = 0; pr < 4; pr++) {
                int c = pr * 2 + (grp >> 1);
                uint32_t off = r * 128 + ((c ^ (r & 7)) << 4);
                uint32_t vh0[2], vh1[2], vl0[2], vl1[2];
                LDSM_X4T(vh0[0], vh0[1], vh1[0], vh1[1], stg + 8192 + off);
                LDSM_X4T(vl0[0], vl0[1], vl1[0], vl1[1], stg + 12288 + off);
                mma16816(oacc[pr*2],   pah[kk2], vh0);
                mma16816(oacc[pr*2],   pal[kk2], vh0);
                mma16816(oacc[pr*2],   pah[kk2], vl0);
                mma16816(oacc[pr*2+1], pah[kk2], vh1);
                mma16816(oacc[pr*2+1], pal[kk2], vh1);
                mma16816(oacc[pr*2+1], pah[kk2], vl1);
            }
        }
    }

    // ---- epilogue: normalize + split-fp16 store ----
    const float inv0 = 1.f / l0, inv1 = 1.f / l1;
    const size_t r0 = (size_t)(mbase + qt * 64 + w * 16 + g);
    const size_t r1 = r0 + 8;
#pragma unroll
    for (int nt = 0; nt < 8; nt++) {
        int c = qcol + nt * 8 + tig * 2;
        float v00 = oacc[nt][0] * inv0, v01 = oacc[nt][1] * inv0;
        float v10 = oacc[nt][2] * inv1, v11 = oacc[nt][3] * inv1;
        __half2 h0 = __floats2half2_rn(v00, v01);
        __half2 h1 = __floats2half2_rn(v10, v11);
        *(__half2*)&ohi[r0 * DIM + c] = h0;
        *(__half2*)&ohi[r1 * DIM + c] = h1;
        *(__half2*)&olo[r0 * DIM + c] =
            __floats2half2_rn(v00 - __low2float(h0), v01 - __high2float(h0));
        *(__half2*)&olo[r1 * DIM + c] =
            __floats2half2_rn(v10 - __low2float(h1), v11 - __high2float(h1));
    }
}

// ---------------------------------------------------------------------------
extern "C" void kernel_launch(void* const* d_in, const int* in_sizes, int n_in,
                              void* d_out, int out_size)
{
    (void)in_sizes; (void)n_in; (void)out_size;
    const float* x     = (const float*)d_in[0];
    const float* w_qkv = (const float*)d_in[1];
    const float* b_qkv = (const float*)d_in[2];
    const float* w_o   = (const float*)d_in[3];
    const float* b_o   = (const float*)d_in[4];
    float* out = (float*)d_out;

    __half *xhi, *xlo, *wqt, *wot, *qkvh, *qkvl, *ahi, *alo;
    cudaGetSymbolAddress((void**)&xhi,  g_xhi);
    cudaGetSymbolAddress((void**)&xlo,  g_xlo);
    cudaGetSymbolAddress((void**)&wqt,  g_wqkvt);
    cudaGetSymbolAddress((void**)&wot,  g_wot);
    cudaGetSymbolAddress((void**)&qkvh, g_qkvh);
    cudaGetSymbolAddress((void**)&qkvl, g_qkvl);
    cudaGetSymbolAddress((void**)&ahi,  g_ahi);
    cudaGetSymbolAddress((void**)&alo,  g_alo);

    // 1) Split x into fp16 hi/lo
    {
        int n4 = MROWS * DIM / 4;
        split_kernel<<<n4 / 256, 256>>>((const float4*)x, xhi, xlo, n4);
    }
    // 2) Transpose weights to fp16
    tsplit_kernel<<<dim3(N3 / 32, DIM / 32), dim3(32, 8)>>>(w_qkv, wqt, DIM, N3);
    tsplit_kernel<<<dim3(DIM / 32, DIM / 32), dim3(32, 8)>>>(w_o, wot, DIM, DIM);

    // 3) QKV projection -> split fp16 output (feeds attention directly)
    gemm_hmma<1><<<dim3(N3 / 128, MROWS / 128), 256>>>(
        xhi, xlo, wqt, b_qkv, nullptr, qkvh, qkvl, MROWS, N3, DIM);

    // 4) Windowed causal attention (split-fp16 HMMA flash)
    attn_hmma<<<dim3(8, 512), 128>>>(qkvh, qkvl, ahi, alo);

    // 5) Output projection -> fp32 final output
    gemm_hmma<0><<<dim3(DIM / 128, MROWS / 128), 256>>>(
        ahi, alo, wot, b_o, out, nullptr, nullptr, MROWS, DIM, DIM);
}

// round 7
// speedup vs baseline: 5.5595x; 1.2699x over previous
#include <cuda_runtime.h>
#include <cuda_fp16.h>
#include <math.h>
#include <stdint.h>

// Problem constants (fixed shapes)
#define BV      4
#define SEQ     4096
#define DIM     1024
#define WIN     512
#define HEADS   16
#define DH      64
#define MROWS   (BV * SEQ)     // 16384
#define N3      (3 * DIM)      // 3072
#define NEG_INF_F (-1e9f)

// ---------------------------------------------------------------------------
// Scratch (device globals: sanctioned workaround for the no-alloc rule)
// ---------------------------------------------------------------------------
__device__ __half g_xh[(size_t)MROWS * DIM];
__device__ __half g_wqkvt[(size_t)N3 * DIM];     // W_qkv^T [N3, K] fp16
__device__ __half g_wot[(size_t)DIM * DIM];      // W_o^T  [N, K] fp16
__device__ __half g_qkvh[(size_t)MROWS * N3];    // 96 MB
__device__ __half g_qkvl[(size_t)MROWS * N3];    // 96 MB
__device__ __half g_ah[(size_t)MROWS * DIM];

// ---------------------------------------------------------------------------
// Helpers (sm_80-portable ISA: mma.sync + cp.async + ldmatrix)
// ---------------------------------------------------------------------------
__device__ __forceinline__ uint32_t smem_u32(const void* p) {
    uint32_t a;
    asm("{ .reg .u64 t; cvta.to.shared.u64 t, %1; cvt.u32.u64 %0, t; }"
        : "=r"(a) : "l"(p));
    return a;
}
#define CP16(dst, src) \
    asm volatile("cp.async.cg.shared.global [%0], [%1], 16;" \
                 :: "r"(dst), "l"(src) : "memory")
#define CP_COMMIT() asm volatile("cp.async.commit_group;" ::: "memory")
#define CP_WAIT1()  asm volatile("cp.async.wait_group 1;" ::: "memory")
#define CP_WAIT0()  asm volatile("cp.async.wait_group 0;" ::: "memory")

#define LDSM_X4(r0, r1, r2, r3, a) \
    asm volatile("ldmatrix.sync.aligned.m8n8.x4.shared.b16 {%0,%1,%2,%3}, [%4];" \
                 : "=r"(r0), "=r"(r1), "=r"(r2), "=r"(r3) : "r"(a))
#define LDSM_X4T(r0, r1, r2, r3, a) \
    asm volatile("ldmatrix.sync.aligned.m8n8.x4.trans.shared.b16 {%0,%1,%2,%3}, [%4];" \
                 : "=r"(r0), "=r"(r1), "=r"(r2), "=r"(r3) : "r"(a))

__device__ __forceinline__ void mma16816(float* d, const uint32_t* a, const uint32_t* b) {
    asm volatile(
        "mma.sync.aligned.m16n8k16.row.col.f32.f16.f16.f32 "
        "{%0,%1,%2,%3}, {%4,%5,%6,%7}, {%8,%9}, {%0,%1,%2,%3};"
        : "+f"(d[0]), "+f"(d[1]), "+f"(d[2]), "+f"(d[3])
        : "r"(a[0]), "r"(a[1]), "r"(a[2]), "r"(a[3]), "r"(b[0]), "r"(b[1]));
}

__device__ __forceinline__ uint32_t packh2(float a, float b) {
    __half2 t = __floats2half2_rn(a, b);
    return *reinterpret_cast<uint32_t*>(&t);
}

// ---------------------------------------------------------------------------
// fp16 HMMA GEMM: C[M,N] = A[M,K] @ B^T + bias  (A, B fp16; B stored [N,K])
// CTA 128x128, 256 threads (8 warps, 32x64 warp tiles), BK=32/stage,
// 3-stage cp.async pipeline (48KB), ldmatrix fragment loads.
// SPLIT=0: fp32 C + bias.  SPLIT=1: fp16 hi/lo outputs + bias.
// Smem rows 64B (4 x 16B chunks), phys chunk = chunk ^ ((row>>1)&3);
// k-step 1 of a stage is offset^32 (chunk bit1 flip).
// ---------------------------------------------------------------------------
template<int SPLIT>
__global__ __launch_bounds__(256, 2) void gemm_hmma(
    const __half* __restrict__ A, const __half* __restrict__ Bh,
    const float* __restrict__ bias, float* __restrict__ C,
    __half* __restrict__ Ch, __half* __restrict__ Cl,
    int M, int N, int K)
{
    __shared__ char sm[49152];          // 3 stages x (A 8KB + B 8KB)
    const uint32_t sb = smem_u32(sm);

    const int tid  = threadIdx.x;
    const int lane = tid & 31, wid = tid >> 5;
    const int g = lane >> 2, tig = lane & 3;
    const int jj = lane & 7, grp = lane >> 3;
    const int wm = (wid & 3) * 32;      // 4 warps down M
    const int wn = (wid >> 2) * 64;     // 2 warps across N
    const int row0 = blockIdx.y * 128, col0 = blockIdx.x * 128;

    // cp.async mapping: each thread loads 2 consecutive 16B chunks of one row
    // per buffer (A and B), 4 CP16 per stage.
    const int lr  = tid >> 1;           // row 0..127
    const int lc0 = (tid & 1) * 2;      // first chunk 0 or 2
    const int lsw = (lr >> 1) & 3;
    const uint32_t dA0 = lr * 64 + (((lc0 + 0) ^ lsw) << 4);
    const uint32_t dA1 = lr * 64 + (((lc0 + 1) ^ lsw) << 4);
    const __half* gA0 = A  + (size_t)(row0 + lr) * K + lc0 * 8;
    const __half* gB0 = Bh + (size_t)(col0 + lr) * K + lc0 * 8;

    // ldmatrix per-lane offsets for k-step 0 (k-step 1 = ^32)
    uint32_t aoff[2], boff[4];
#pragma unroll
    for (int mt = 0; mt < 2; mt++) {
        int r = wm + mt * 16 + (grp & 1) * 8 + jj;
        int q = grp >> 1;
        aoff[mt] = r * 64 + ((q ^ ((r >> 1) & 3)) << 4);
    }
#pragma unroll
    for (int bt = 0; bt < 4; bt++) {
        int r = wn + bt * 16 + (grp >> 1) * 8 + jj;
        int q = grp & 1;
        boff[bt] = r * 64 + ((q ^ ((r >> 1) & 3)) << 4);
    }

    float acc[2][8][4];
#pragma unroll
    for (int mt = 0; mt < 2; mt++)
#pragma unroll
        for (int nf = 0; nf < 8; nf++)
#pragma unroll
            for (int j = 0; j < 4; j++) acc[mt][nf][j] = 0.f;

    const int nst = K >> 5;             // 32 stages for K=1024

    // Prologue: stages 0 and 1
#pragma unroll
    for (int s = 0; s < 2; s++) {
        const uint32_t so = s * 16384;
        const int ko = s * 32;
        CP16(sb + so + dA0, gA0 + ko);
        CP16(sb + so + dA1, gA0 + ko + 8);
        CP16(sb + so + 8192 + dA0, gB0 + ko);
        CP16(sb + so + 8192 + dA1, gB0 + ko + 8);
        CP_COMMIT();
    }

    for (int st = 0; st < nst; st++) {
        if (st + 1 < nst) { CP_WAIT1(); } else { CP_WAIT0(); }
        __syncthreads();
        if (st + 2 < nst) {
            const uint32_t so = ((st + 2) % 3) * 16384;
            const int ko = (st + 2) * 32;
            CP16(sb + so + dA0, gA0 + ko);
            CP16(sb + so + dA1, gA0 + ko + 8);
            CP16(sb + so + 8192 + dA0, gB0 + ko);
            CP16(sb + so + 8192 + dA1, gB0 + ko + 8);
            CP_COMMIT();
        }

        const uint32_t base = sb + (st % 3) * 16384;
#pragma unroll
        for (int ks = 0; ks < 2; ks++) {
            const uint32_t x = ks << 5;
            uint32_t ah[2][4], bh[8][2];
            LDSM_X4(ah[0][0], ah[0][1], ah[0][2], ah[0][3], base + (aoff[0] ^ x));
            LDSM_X4(ah[1][0], ah[1][1], ah[1][2], ah[1][3], base + (aoff[1] ^ x));
#pragma unroll
            for (int bt = 0; bt < 4; bt++)
                LDSM_X4(bh[2*bt][0], bh[2*bt][1], bh[2*bt+1][0], bh[2*bt+1][1],
                        base + 8192 + (boff[bt] ^ x));
#pragma unroll
            for (int mt = 0; mt < 2; mt++)
#pragma unroll
                for (int nf = 0; nf < 8; nf++)
                    mma16816(acc[mt][nf], ah[mt], bh[nf]);
        }
    }

#pragma unroll
    for (int mt = 0; mt < 2; mt++) {
        const int r = row0 + wm + mt * 16 + g;
#pragma unroll
        for (int nf = 0; nf < 8; nf++) {
            const int c = col0 + wn + nf * 8 + tig * 2;
            const float bx = bias[c], by = bias[c + 1];
            float v00 = acc[mt][nf][0] + bx, v01 = acc[mt][nf][1] + by;
            float v10 = acc[mt][nf][2] + bx, v11 = acc[mt][nf][3] + by;
            if (SPLIT) {
                __half2 h0 = __floats2half2_rn(v00, v01);
                __half2 h1 = __floats2half2_rn(v10, v11);
                __half2 l0 = __floats2half2_rn(v00 - __low2float(h0),
                                               v01 - __high2float(h0));
                __half2 l1 = __floats2half2_rn(v10 - __low2float(h1),
                                               v11 - __high2float(h1));
                *(__half2*)&Ch[(size_t)r * N + c]       = h0;
                *(__half2*)&Ch[(size_t)(r + 8) * N + c] = h1;
                *(__half2*)&Cl[(size_t)r * N + c]       = l0;
                *(__half2*)&Cl[(size_t)(r + 8) * N + c] = l1;
            } else {
                float2 a0 = { v00, v01 }, a1 = { v10, v11 };
                *(float2*)&C[(size_t)r * N + c]       = a0;
                *(float2*)&C[(size_t)(r + 8) * N + c] = a1;
            }
        }
    }
}

// ---------------------------------------------------------------------------
// fp32 -> fp16 convert (elementwise)
// ---------------------------------------------------------------------------
__global__ __launch_bounds__(256) void cvt_kernel(
    const float4* __restrict__ in, __half* __restrict__ hi, int n4)
{
    int i = blockIdx.x * 256 + threadIdx.x;
    if (i >= n4) return;
    float4 v = in[i];
    ((__half2*)hi)[2 * i + 0] = __floats2half2_rn(v.x, v.y);
    ((__half2*)hi)[2 * i + 1] = __floats2half2_rn(v.z, v.w);
}

// ---------------------------------------------------------------------------
// Transpose: W [K, N] fp32 -> Wt [N, K] fp16 (weights)
// ---------------------------------------------------------------------------
__global__ __launch_bounds__(256) void tsplit_kernel(
    const float* __restrict__ W, __half* __restrict__ Th, int K, int N)
{
    __shared__ float t[32][33];
    const int nb = blockIdx.x * 32, kb = blockIdx.y * 32;
    const int tx = threadIdx.x, ty = threadIdx.y;
    for (int y = ty; y < 32; y += 8)
        t[y][tx] = W[(size_t)(kb + y) * N + nb + tx];
    __syncthreads();
    for (int y = ty; y < 32; y += 8)
        Th[(size_t)(nb + y) * K + kb + tx] = __float2half(t[tx][y]);
}

// ---------------------------------------------------------------------------
// Windowed causal attention, split-fp16 HMMA flash kernel (3-product).
// Block: 128 threads (4 warps). Grid: (8 q-tiles of 64 rows, 32 win x 16 heads).
// Smem (48KB): Qh 8K | Ql 8K | stage{0,1}: Kh 4K, Kl 4K, Vh 4K, Vl 4K.
// Tile rows are 128B (8 x 16B chunks); phys chunk = chunk ^ (row & 7).
// Epilogue writes fp16 hi only (GEMM2 is 1-product).
// ---------------------------------------------------------------------------
__device__ __forceinline__ void attn_load_kv(
    uint32_t sstage, const __half* qh_g, const __half* ql_g,
    size_t rowbase, int tid)
{
#pragma unroll
    for (int it = 0; it < 8; it++) {
        int i = tid + it * 128;
        int buf = i >> 8, within = i & 255;
        int r = within >> 3, c = within & 7;
        uint32_t dst = sstage + buf * 4096 + r * 128 + ((c ^ (r & 7)) << 4);
        size_t go = rowbase + (size_t)r * N3 + c * 8;
        const __half* src;
        if (buf == 0)      src = qh_g + go + DIM;       // Kh
        else if (buf == 1) src = ql_g + go + DIM;       // Kl
        else if (buf == 2) src = qh_g + go + 2 * DIM;   // Vh
        else               src = ql_g + go + 2 * DIM;   // Vl
        CP16(dst, src);
    }
}

__global__ __launch_bounds__(128) void attn_hmma(
    const __half* __restrict__ qh_g, const __half* __restrict__ ql_g,
    __half* __restrict__ oh)
{
    const int qt  = blockIdx.x;          // 0..7
    const int wh  = blockIdx.y;          // 0..511
    const int win = wh >> 4, h = wh & 15;
    const int mbase = win * WIN;
    const int qcol  = h * DH;
    const int tid = threadIdx.x, lane = tid & 31, w = tid >> 5;
    const int g = lane >> 2, tig = lane & 3;
    const int jj = lane & 7, grp = lane >> 3;

    __shared__ char sm[49152];
    const uint32_t sb = smem_u32(sm);

    // Load Q tile [64 x 64] hi/lo (vectorized stores, swizzled)
    for (int i = tid; i < 512; i += 128) {
        int r = i >> 3, c = i & 7;
        uint32_t off = r * 128 + ((c ^ (r & 7)) << 4);
        size_t gsrc = (size_t)(mbase + qt * 64 + r) * N3 + qcol + c * 8;
        *(uint4*)(sm + off)        = *(const uint4*)(qh_g + gsrc);
        *(uint4*)(sm + 8192 + off) = *(const uint4*)(ql_g + gsrc);
    }

    const int ktmax = 2 * qt + 1;
    attn_load_kv(sb + 16384, qh_g, ql_g, (size_t)mbase * N3 + qcol, tid);
    CP_COMMIT();
    __syncthreads();

    // Q fragments (registers, whole block)
    uint32_t qfh[4][4], qfl[4][4];
    const int qrow = w * 16 + (grp & 1) * 8 + jj;
#pragma unroll
    for (int kk = 0; kk < 4; kk++) {
        int c = 2 * kk + (grp >> 1);
        uint32_t off = qrow * 128 + ((c ^ (qrow & 7)) << 4);
        LDSM_X4(qfh[kk][0], qfh[kk][1], qfh[kk][2], qfh[kk][3], sb + off);
        LDSM_X4(qfl[kk][0], qfl[kk][1], qfl[kk][2], qfl[kk][3], sb + 8192 + off);
    }

    float m0 = -INFINITY, m1 = -INFINITY, l0 = 0.f, l1 = 0.f;
    float oacc[8][4];
#pragma unroll
    for (int nt = 0; nt < 8; nt++)
#pragma unroll
        for (int j = 0; j < 4; j++) oacc[nt][j] = 0.f;

    const int gq0 = qt * 64 + w * 16 + g;
    const int gq1 = gq0 + 8;
    const int krowb = (grp >> 1) * 8 + jj;
    const int vrow0 = (grp & 1) * 8 + jj;

    for (int kt = 0; kt <= ktmax; kt++) {
        CP_WAIT0();
        __syncthreads();
        if (kt < ktmax) {
            attn_load_kv(sb + 16384 + ((kt + 1) & 1) * 16384, qh_g, ql_g,
                         (size_t)(mbase + (kt + 1) * 32) * N3 + qcol, tid);
            CP_COMMIT();
        }

        const uint32_t stg = sb + 16384 + (kt & 1) * 16384;

        // ---- S = Q K^T (split, 3 products) ----
        float sacc[4][4];
#pragma unroll
        for (int nt = 0; nt < 4; nt++)
#pragma unroll
            for (int j = 0; j < 4; j++) sacc[nt][j] = 0.f;

#pragma unroll
        for (int kk = 0; kk < 4; kk++) {
            uint32_t kbh[4][2], kbl[4][2];
#pragma unroll
            for (int pr = 0; pr < 2; pr++) {
                int r = pr * 16 + krowb;
                int c = 2 * kk + (grp & 1);
                uint32_t off = r * 128 + ((c ^ (r & 7)) << 4);
                LDSM_X4(kbh[pr*2][0], kbh[pr*2][1], kbh[pr*2+1][0], kbh[pr*2+1][1],
                        stg + off);
                LDSM_X4(kbl[pr*2][0], kbl[pr*2][1], kbl[pr*2+1][0], kbl[pr*2+1][1],
                        stg + 4096 + off);
            }
#pragma unroll
            for (int nt = 0; nt < 4; nt++) {
                mma16816(sacc[nt], qfh[kk], kbh[nt]);
                mma16816(sacc[nt], qfh[kk], kbl[nt]);
                mma16816(sacc[nt], qfl[kk], kbh[nt]);
            }
        }

        // ---- scale + causal mask ----
#pragma unroll
        for (int nt = 0; nt < 4; nt++) {
            int colb = kt * 32 + nt * 8 + 2 * tig;
            sacc[nt][0] = (colb     > gq0) ? NEG_INF_F : sacc[nt][0] * 0.125f;
            sacc[nt][1] = (colb + 1 > gq0) ? NEG_INF_F : sacc[nt][1] * 0.125f;
            sacc[nt][2] = (colb     > gq1) ? NEG_INF_F : sacc[nt][2] * 0.125f;
            sacc[nt][3] = (colb + 1 > gq1) ? NEG_INF_F : sacc[nt][3] * 0.125f;
        }

        // ---- online softmax (rows g, g+8; reduce over tig lanes) ----
        float rm0 = fmaxf(fmaxf(sacc[0][0], sacc[0][1]), fmaxf(sacc[1][0], sacc[1][1]));
        rm0 = fmaxf(rm0, fmaxf(fmaxf(sacc[2][0], sacc[2][1]), fmaxf(sacc[3][0], sacc[3][1])));
        float rm1 = fmaxf(fmaxf(sacc[0][2], sacc[0][3]), fmaxf(sacc[1][2], sacc[1][3]));
        rm1 = fmaxf(rm1, fmaxf(fmaxf(sacc[2][2], sacc[2][3]), fmaxf(sacc[3][2], sacc[3][3])));
        rm0 = fmaxf(rm0, __shfl_xor_sync(0xffffffffu, rm0, 1));
        rm0 = fmaxf(rm0, __shfl_xor_sync(0xffffffffu, rm0, 2));
        rm1 = fmaxf(rm1, __shfl_xor_sync(0xffffffffu, rm1, 1));
        rm1 = fmaxf(rm1, __shfl_xor_sync(0xffffffffu, rm1, 2));

        float mn0 = fmaxf(m0, rm0), mn1 = fmaxf(m1, rm1);
        float corr0 = __expf(m0 - mn0), corr1 = __expf(m1 - mn1);
        m0 = mn0; m1 = mn1;

        float rs0 = 0.f, rs1 = 0.f;
#pragma unroll
        for (int nt = 0; nt < 4; nt++) {
            sacc[nt][0] = __expf(sacc[nt][0] - mn0);
            sacc[nt][1] = __expf(sacc[nt][1] - mn0);
            sacc[nt][2] = __expf(sacc[nt][2] - mn1);
            sacc[nt][3] = __expf(sacc[nt][3] - mn1);
            rs0 += sacc[nt][0] + sacc[nt][1];
            rs1 += sacc[nt][2] + sacc[nt][3];
        }
        rs0 += __shfl_xor_sync(0xffffffffu, rs0, 1);
        rs0 += __shfl_xor_sync(0xffffffffu, rs0, 2);
        rs1 += __shfl_xor_sync(0xffffffffu, rs1, 1);
        rs1 += __shfl_xor_sync(0xffffffffu, rs1, 2);
        l0 = l0 * corr0 + rs0;
        l1 = l1 * corr1 + rs1;

#pragma unroll
        for (int nt = 0; nt < 8; nt++) {
            oacc[nt][0] *= corr0; oacc[nt][1] *= corr0;
            oacc[nt][2] *= corr1; oacc[nt][3] *= corr1;
        }

        // ---- P fragments (FA2 identity: C-frag == A-frag layout) ----
        uint32_t pah[2][4], pal[2][4];
#pragma unroll
        for (int kk2 = 0; kk2 < 2; kk2++) {
            int a = 2 * kk2, b = a + 1;
            pah[kk2][0] = packh2(sacc[a][0], sacc[a][1]);
            pah[kk2][1] = packh2(sacc[a][2], sacc[a][3]);
            pah[kk2][2] = packh2(sacc[b][0], sacc[b][1]);
            pah[kk2][3] = packh2(sacc[b][2], sacc[b][3]);
            __half2* t;
            t = (__half2*)&pah[kk2][0];
            pal[kk2][0] = packh2(sacc[a][0] - __low2float(*t),
                                 sacc[a][1] - __high2float(*t));
            t = (__half2*)&pah[kk2][1];
            pal[kk2][1] = packh2(sacc[a][2] - __low2float(*t),
                                 sacc[a][3] - __high2float(*t));
            t = (__half2*)&pah[kk2][2];
            pal[kk2][2] = packh2(sacc[b][0] - __low2float(*t),
                                 sacc[b][1] - __high2float(*t));
            t = (__half2*)&pah[kk2][3];
            pal[kk2][3] = packh2(sacc[b][2] - __low2float(*t),
                                 sacc[b][3] - __high2float(*t));
        }

        // ---- O += P V (split, 3 products); V via ldmatrix.trans ----
#pragma unroll
        for (int kk2 = 0; kk2 < 2; kk2++) {
            int r = kk2 * 16 + vrow0;
#pragma unroll
            for (int pr = 0; pr < 4; pr++) {
                int c = pr * 2 + (grp >> 1);
                uint32_t off = r * 128 + ((c ^ (r & 7)) << 4);
                uint32_t vh0[2], vh1[2], vl0[2], vl1[2];
                LDSM_X4T(vh0[0], vh0[1], vh1[0], vh1[1], stg + 8192 + off);
                LDSM_X4T(vl0[0], vl0[1], vl1[0], vl1[1], stg + 12288 + off);
                mma16816(oacc[pr*2],   pah[kk2], vh0);
                mma16816(oacc[pr*2],   pal[kk2], vh0);
                mma16816(oacc[pr*2],   pah[kk2], vl0);
                mma16816(oacc[pr*2+1], pah[kk2], vh1);
                mma16816(oacc[pr*2+1], pal[kk2], vh1);
                mma16816(oacc[pr*2+1], pah[kk2], vl1);
            }
        }
    }

    // ---- epilogue: normalize + fp16 store (hi only) ----
    const float inv0 = 1.f / l0, inv1 = 1.f / l1;
    const size_t r0 = (size_t)(mbase + qt * 64 + w * 16 + g);
    const size_t r1 = r0 + 8;
#pragma unroll
    for (int nt = 0; nt < 8; nt++) {
        int c = qcol + nt * 8 + tig * 2;
        *(__half2*)&oh[r0 * DIM + c] =
            __floats2half2_rn(oacc[nt][0] * inv0, oacc[nt][1] * inv0);
        *(__half2*)&oh[r1 * DIM + c] =
            __floats2half2_rn(oacc[nt][2] * inv1, oacc[nt][3] * inv1);
    }
}

// ---------------------------------------------------------------------------
extern "C" void kernel_launch(void* const* d_in, const int* in_sizes, int n_in,
                              void* d_out, int out_size)
{
    (void)in_sizes; (void)n_in; (void)out_size;
    const float* x     = (const float*)d_in[0];
    const float* w_qkv = (const float*)d_in[1];
    const float* b_qkv = (const float*)d_in[2];
    const float* w_o   = (const float*)d_in[3];
    const float* b_o   = (const float*)d_in[4];
    float* out = (float*)d_out;

    __half *xh, *wqt, *wot, *qkvh, *qkvl, *ah;
    cudaGetSymbolAddress((void**)&xh,   g_xh);
    cudaGetSymbolAddress((void**)&wqt,  g_wqkvt);
    cudaGetSymbolAddress((void**)&wot,  g_wot);
    cudaGetSymbolAddress((void**)&qkvh, g_qkvh);
    cudaGetSymbolAddress((void**)&qkvl, g_qkvl);
    cudaGetSymbolAddress((void**)&ah,   g_ah);

    // 1) Convert x to fp16
    {
        int n4 = MROWS * DIM / 4;
        cvt_kernel<<<n4 / 256, 256>>>((const float4*)x, xh, n4);
    }
    // 2) Transpose weights to fp16
    tsplit_kernel<<<dim3(N3 / 32, DIM / 32), dim3(32, 8)>>>(w_qkv, wqt, DIM, N3);
    tsplit_kernel<<<dim3(DIM / 32, DIM / 32), dim3(32, 8)>>>(w_o, wot, DIM, DIM);

    // 3) QKV projection -> fp16 hi/lo output (feeds attention's 3-product path)
    gemm_hmma<1><<<dim3(N3 / 128, MROWS / 128), 256>>>(
        xh, wqt, b_qkv, nullptr, qkvh, qkvl, MROWS, N3, DIM);

    // 4) Windowed causal attention (split-fp16 HMMA flash) -> fp16 hi
    attn_hmma<<<dim3(8, 512), 128>>>(qkvh, qkvl, ah);

    // 5) Output projection -> fp32 final output
    gemm_hmma<0><<<dim3(DIM / 128, MROWS / 128), 256>>>(
        ah, wot, b_o, out, nullptr, nullptr, MROWS, DIM, DIM);
}